// round 4
// baseline (speedup 1.0000x reference)
#include <cuda_runtime.h>
#include <cuda_bf16.h>
#include <cstdint>
#include <math.h>

#define BATCH 8192
#define DHALF 1024
#define HID   4096
#define XCOLS 2048
#define WSLOT ((size_t)DHALF * HID)

// ---------------- scratch (device globals: allocation-free rule) -----------
__device__ __nv_bfloat16 g_act_hi[(size_t)BATCH * DHALF];
__device__ __nv_bfloat16 g_act_lo[(size_t)BATCH * DHALF];
__device__ __nv_bfloat16 g_hid_hi[(size_t)BATCH * HID];
__device__ __nv_bfloat16 g_hid_lo[(size_t)BATCH * HID];
__device__ __nv_bfloat16 g_wt_hi[8 * WSLOT];
__device__ __nv_bfloat16 g_wt_lo[8 * WSLOT];
__device__ float g_s[(size_t)BATCH * DHALF];
__device__ float g_t[(size_t)BATCH * DHALF];

// ---------------- helpers ----------------------------------------------
__device__ __forceinline__ uint32_t smem_u32(const void* p) {
    uint32_t a;
    asm("{ .reg .u64 t; cvta.to.shared.u64 t, %1; cvt.u32.u64 %0, t; }" : "=r"(a) : "l"(p));
    return a;
}
__device__ __forceinline__ void cp16(uint32_t s, const void* g) {
    asm volatile("cp.async.cg.shared.global [%0], [%1], 16;" :: "r"(s), "l"(g));
}
__device__ __forceinline__ void split_bf(float v, __nv_bfloat16& hi, __nv_bfloat16& lo) {
    hi = __float2bfloat16(v);
    lo = __float2bfloat16(v - __bfloat162float(hi));
}
__device__ __forceinline__ uint32_t pack_bf2(__nv_bfloat16 a, __nv_bfloat16 b) {
    __nv_bfloat162 t = __halves2bfloat162(a, b);
    return *reinterpret_cast<uint32_t*>(&t);
}
__device__ __forceinline__ void mma16816(float* d, const uint32_t* a, uint32_t b0, uint32_t b1) {
    asm volatile(
        "mma.sync.aligned.m16n8k16.row.col.f32.bf16.bf16.f32 "
        "{%0,%1,%2,%3}, {%4,%5,%6,%7}, {%8,%9}, {%0,%1,%2,%3};"
        : "+f"(d[0]), "+f"(d[1]), "+f"(d[2]), "+f"(d[3])
        : "r"(a[0]), "r"(a[1]), "r"(a[2]), "r"(a[3]), "r"(b0), "r"(b1));
}
__device__ __forceinline__ void ldsm4(uint32_t* r, uint32_t addr) {
    asm volatile("ldmatrix.sync.aligned.m8n8.x4.shared.b16 {%0,%1,%2,%3}, [%4];"
        : "=r"(r[0]), "=r"(r[1]), "=r"(r[2]), "=r"(r[3]) : "r"(addr));
}

// ---------------------------------------------------------------------------
// bf16x3 split GEMM on mma.sync + ldmatrix.
// Block 128x128, BK=64, 3-stage cp.async pipeline, 8 warps (2m x 4n),
// warp tile 64x32. Smem rows padded to 144B (36 banks) -> ldmatrix conflict-free.
// ---------------------------------------------------------------------------
#define BM 128
#define BN 128
#define BK 64
#define STAGES 3
#define PITCH  144u
#define TILEB  (128u * PITCH)            // 18432 B per matrix tile
#define STAGEB (4u * TILEB)              // Ahi,Alo,Bhi,Blo = 73728
#define SMEM_BYTES (STAGES * STAGEB)     // 221184

template<bool RELU, bool BF16OUT>
__global__ __launch_bounds__(256, 1)
void gemm_mma_x3(const __nv_bfloat16* __restrict__ Ahi, const __nv_bfloat16* __restrict__ Alo,
                 const __nv_bfloat16* __restrict__ Bhi, const __nv_bfloat16* __restrict__ Blo,
                 const float* __restrict__ bias,
                 float* __restrict__ Cf,
                 __nv_bfloat16* __restrict__ Chi, __nv_bfloat16* __restrict__ Clo,
                 int K, int N)
{
    extern __shared__ char smem[];
    const uint32_t sb = smem_u32(smem);
    const int tid = threadIdx.x;
    const int wid = tid >> 5;
    const int lid = tid & 31;
    const int wm = wid & 1;
    const int wn = wid >> 1;
    const int mBase = blockIdx.y * BM;
    const int nBase = blockIdx.x * BN;

    auto load_stage = [&](int stage, int k0) {
        const uint32_t st = sb + stage * STAGEB;
        #pragma unroll
        for (int j = 0; j < 4; ++j) {
            int i = tid + 256 * j;            // 0..1023
            int r = i >> 3, c = i & 7;        // row 0..127, 16B chunk 0..7
            uint32_t off = (uint32_t)r * PITCH + (uint32_t)c * 16u;
            size_t ga = (size_t)(mBase + r) * K + k0 + c * 8;
            size_t gb = (size_t)(nBase + r) * K + k0 + c * 8;
            cp16(st + off,             Ahi + ga);
            cp16(st + TILEB + off,     Alo + ga);
            cp16(st + 2 * TILEB + off, Bhi + gb);
            cp16(st + 3 * TILEB + off, Blo + gb);
        }
        asm volatile("cp.async.commit_group;" ::: "memory");
    };

    float acc[4][4][4];
    #pragma unroll
    for (int i = 0; i < 4; ++i)
        #pragma unroll
        for (int j = 0; j < 4; ++j)
            #pragma unroll
            for (int q = 0; q < 4; ++q) acc[i][j][q] = 0.f;

    const int NC = K / BK;
    load_stage(0, 0);
    load_stage(1, BK);
    load_stage(2, 2 * BK);

    // ldmatrix lane addressing
    const int lr16  = lid & 15;                 // row within 16-row tile
    const uint32_t lcol = (uint32_t)(lid >> 4) * 16u;  // 0 or 16 bytes (k half)

    for (int c = 0; c < NC; ++c) {
        const int s = c % STAGES;
        asm volatile("cp.async.wait_group %0;" :: "n"(STAGES - 1) : "memory");
        __syncthreads();

        const uint32_t st = sb + s * STAGEB;
        const uint32_t aAddr = st + (uint32_t)(wm * 64 + lr16) * PITCH + lcol;
        const uint32_t bAddr = st + 2 * TILEB + (uint32_t)(wn * 32 + lr16) * PITCH + lcol;

        #pragma unroll
        for (int kb = 0; kb < 4; ++kb) {
            const uint32_t cOff = (uint32_t)kb * 32u;
            uint32_t ah[4][4], al[4][4], bh[2][4], bl[2][4];
            #pragma unroll
            for (int mi = 0; mi < 4; ++mi) {
                ldsm4(ah[mi], aAddr + (uint32_t)mi * (16u * PITCH) + cOff);
                ldsm4(al[mi], aAddr + TILEB + (uint32_t)mi * (16u * PITCH) + cOff);
            }
            #pragma unroll
            for (int g = 0; g < 2; ++g) {
                ldsm4(bh[g], bAddr + (uint32_t)g * (16u * PITCH) + cOff);
                ldsm4(bl[g], bAddr + TILEB + (uint32_t)g * (16u * PITCH) + cOff);
            }
            #pragma unroll
            for (int mi = 0; mi < 4; ++mi)
                #pragma unroll
                for (int ni = 0; ni < 4; ++ni)
                    mma16816(acc[mi][ni], ah[mi], bh[ni >> 1][ni & 1], bh[ni >> 1][(ni & 1) + 2]);
            #pragma unroll
            for (int mi = 0; mi < 4; ++mi)
                #pragma unroll
                for (int ni = 0; ni < 4; ++ni)
                    mma16816(acc[mi][ni], ah[mi], bl[ni >> 1][ni & 1], bl[ni >> 1][(ni & 1) + 2]);
            #pragma unroll
            for (int mi = 0; mi < 4; ++mi)
                #pragma unroll
                for (int ni = 0; ni < 4; ++ni)
                    mma16816(acc[mi][ni], al[mi], bh[ni >> 1][ni & 1], bh[ni >> 1][(ni & 1) + 2]);
        }

        __syncthreads();
        if (c + STAGES < NC) load_stage(s, (c + STAGES) * BK);
    }

    // ---- epilogue ----
    const int lr = lid >> 2;
    const int q2 = (lid & 3) * 2;
    #pragma unroll
    for (int mi = 0; mi < 4; ++mi) {
        #pragma unroll
        for (int half = 0; half < 2; ++half) {
            const int m = mBase + wm * 64 + mi * 16 + lr + half * 8;
            #pragma unroll
            for (int ni = 0; ni < 4; ++ni) {
                const int n = nBase + wn * 32 + ni * 8 + q2;
                float v0 = acc[mi][ni][half * 2 + 0] + bias[n];
                float v1 = acc[mi][ni][half * 2 + 1] + bias[n + 1];
                if (RELU) { v0 = fmaxf(v0, 0.f); v1 = fmaxf(v1, 0.f); }
                if (BF16OUT) {
                    __nv_bfloat16 h0, h1, l0, l1;
                    split_bf(v0, h0, l0);
                    split_bf(v1, h1, l1);
                    *reinterpret_cast<uint32_t*>(&Chi[(size_t)m * N + n]) = pack_bf2(h0, h1);
                    *reinterpret_cast<uint32_t*>(&Clo[(size_t)m * N + n]) = pack_bf2(l0, l1);
                } else {
                    *reinterpret_cast<float2*>(&Cf[(size_t)m * N + n]) = make_float2(v0, v1);
                }
            }
        }
    }
}

// ---------------------------------------------------------------------------
// Fused weight converter: 8 matrices in one launch (blockIdx.z = matrix).
// W[K,N] fp32 -> WT[N,K] bf16 hi/lo (transpose + split).
// even z: K=1024,N=4096; odd z: K=4096,N=1024. grid (128, 32, 8).
// ---------------------------------------------------------------------------
__global__ __launch_bounds__(256)
void convert_wT8(const float* __restrict__ W0, const float* __restrict__ W1,
                 const float* __restrict__ W2, const float* __restrict__ W3,
                 const float* __restrict__ W4, const float* __restrict__ W5,
                 const float* __restrict__ W6, const float* __restrict__ W7,
                 __nv_bfloat16* __restrict__ Thi, __nv_bfloat16* __restrict__ Tlo)
{
    const int z = blockIdx.z;
    const float* Ws[8] = {W0, W1, W2, W3, W4, W5, W6, W7};
    const float* W = Ws[z];
    const int K = (z & 1) ? HID : DHALF;
    const int N = (z & 1) ? DHALF : HID;
    const int n0 = (z & 1) ? blockIdx.y * 32 : blockIdx.x * 32;
    const int k0 = (z & 1) ? blockIdx.x * 32 : blockIdx.y * 32;
    __nv_bfloat16* thi = Thi + (size_t)z * WSLOT;
    __nv_bfloat16* tlo = Tlo + (size_t)z * WSLOT;

    __shared__ float t[32][33];
    const int tx = threadIdx.x & 31, ty = threadIdx.x >> 5;
    #pragma unroll
    for (int i = 0; i < 4; ++i)
        t[ty + i * 8][tx] = W[(size_t)(k0 + ty + i * 8) * N + n0 + tx];
    __syncthreads();
    #pragma unroll
    for (int i = 0; i < 4; ++i) {
        int n = n0 + ty + i * 8;
        float v = t[tx][ty + i * 8];
        __nv_bfloat16 hi, lo;
        split_bf(v, hi, lo);
        thi[(size_t)n * K + k0 + tx] = hi;
        tlo[(size_t)n * K + k0 + tx] = lo;
    }
}

__global__ __launch_bounds__(256)
void convert_act(const float* __restrict__ x,
                 __nv_bfloat16* __restrict__ hi, __nv_bfloat16* __restrict__ lo)
{
    const int m = blockIdx.x;
    const int j = threadIdx.x * 4;
    float4 v = *reinterpret_cast<const float4*>(&x[(size_t)m * XCOLS + DHALF + j]);
    __nv_bfloat16 h0, h1, h2, h3, l0, l1, l2, l3;
    split_bf(v.x, h0, l0); split_bf(v.y, h1, l1);
    split_bf(v.z, h2, l2); split_bf(v.w, h3, l3);
    *reinterpret_cast<uint2*>(&hi[(size_t)m * DHALF + j]) = make_uint2(pack_bf2(h0, h1), pack_bf2(h2, h3));
    *reinterpret_cast<uint2*>(&lo[(size_t)m * DHALF + j]) = make_uint2(pack_bf2(l0, l1), pack_bf2(l2, l3));
}

// ---------------------------------------------------------------------------
// Coupling epilogue
// ---------------------------------------------------------------------------
__global__ __launch_bounds__(256)
void ew_couple(const float* __restrict__ x,
               const float* __restrict__ spre,
               const float* __restrict__ tval,
               float* __restrict__ y,
               float* __restrict__ logdet,
               __nv_bfloat16* __restrict__ acthi, __nv_bfloat16* __restrict__ actlo,
               int xColOff, int yColOff, int addLogdet, int writeAct)
{
    const int m = blockIdx.x;
    const int j = threadIdx.x * 4;

    float4 sp = *reinterpret_cast<const float4*>(&spre[(size_t)m * DHALF + j]);
    float4 tv = *reinterpret_cast<const float4*>(&tval[(size_t)m * DHALF + j]);
    float4 xv = *reinterpret_cast<const float4*>(&x[(size_t)m * XCOLS + xColOff + j]);

    float s0 = tanhf(sp.x), s1 = tanhf(sp.y), s2 = tanhf(sp.z), s3 = tanhf(sp.w);

    float4 o;
    o.x = xv.x * expf(s0) + tv.x;
    o.y = xv.y * expf(s1) + tv.y;
    o.z = xv.z * expf(s2) + tv.z;
    o.w = xv.w * expf(s3) + tv.w;
    *reinterpret_cast<float4*>(&y[(size_t)m * XCOLS + yColOff + j]) = o;

    if (writeAct) {
        __nv_bfloat16 h0, h1, h2, h3, l0, l1, l2, l3;
        split_bf(o.x, h0, l0); split_bf(o.y, h1, l1);
        split_bf(o.z, h2, l2); split_bf(o.w, h3, l3);
        *reinterpret_cast<uint2*>(&acthi[(size_t)m * DHALF + j]) = make_uint2(pack_bf2(h0, h1), pack_bf2(h2, h3));
        *reinterpret_cast<uint2*>(&actlo[(size_t)m * DHALF + j]) = make_uint2(pack_bf2(l0, l1), pack_bf2(l2, l3));
    }

    float lsum = s0 + s1 + s2 + s3;
    #pragma unroll
    for (int off = 16; off > 0; off >>= 1)
        lsum += __shfl_xor_sync(0xFFFFFFFFu, lsum, off);

    __shared__ float wsum[8];
    if ((threadIdx.x & 31) == 0) wsum[threadIdx.x >> 5] = lsum;
    __syncthreads();
    if (threadIdx.x == 0) {
        float tot = 0.0f;
        #pragma unroll
        for (int w = 0; w < 8; ++w) tot += wsum[w];
        if (addLogdet) logdet[m] += tot;
        else           logdet[m]  = tot;
    }
}

// ---------------------------------------------------------------------------
extern "C" void kernel_launch(void* const* d_in, const int* in_sizes, int n_in,
                              void* d_out, int out_size)
{
    (void)in_sizes; (void)n_in; (void)out_size;

    const float* x = (const float*)d_in[0];
    const float* W[8] = { (const float*)d_in[1],  (const float*)d_in[3],
                          (const float*)d_in[5],  (const float*)d_in[7],
                          (const float*)d_in[9],  (const float*)d_in[11],
                          (const float*)d_in[13], (const float*)d_in[15] };
    const float* B[8] = { (const float*)d_in[2],  (const float*)d_in[4],
                          (const float*)d_in[6],  (const float*)d_in[8],
                          (const float*)d_in[10], (const float*)d_in[12],
                          (const float*)d_in[14], (const float*)d_in[16] };

    float* y      = (float*)d_out;
    float* logdet = y + (size_t)BATCH * XCOLS;

    __nv_bfloat16 *acthi, *actlo, *hidhi, *hidlo, *wthi, *wtlo;
    float *sbuf, *tbuf;
    cudaGetSymbolAddress((void**)&acthi, g_act_hi);
    cudaGetSymbolAddress((void**)&actlo, g_act_lo);
    cudaGetSymbolAddress((void**)&hidhi, g_hid_hi);
    cudaGetSymbolAddress((void**)&hidlo, g_hid_lo);
    cudaGetSymbolAddress((void**)&wthi,  g_wt_hi);
    cudaGetSymbolAddress((void**)&wtlo,  g_wt_lo);
    cudaGetSymbolAddress((void**)&sbuf,  g_s);
    cudaGetSymbolAddress((void**)&tbuf,  g_t);

    cudaFuncSetAttribute(gemm_mma_x3<true,  true >, cudaFuncAttributeMaxDynamicSharedMemorySize, SMEM_BYTES);
    cudaFuncSetAttribute(gemm_mma_x3<false, false>, cudaFuncAttributeMaxDynamicSharedMemorySize, SMEM_BYTES);

    // launch #0: all weight converts; #1: act convert; #2..: GEMMs (ncu -s 5 lands on a GEMM)
    convert_wT8<<<dim3(128, 32, 8), 256>>>(W[0], W[1], W[2], W[3], W[4], W[5], W[6], W[7], wthi, wtlo);
    convert_act<<<BATCH, 256>>>(x, acthi, actlo);

    dim3 blk(256);
    dim3 gridH(HID / BN,   BATCH / BM);
    dim3 gridD(DHALF / BN, BATCH / BM);

    // phase 1
    gemm_mma_x3<true,  true ><<<gridH, blk, SMEM_BYTES>>>(acthi, actlo, wthi + 0 * WSLOT, wtlo + 0 * WSLOT, B[0], nullptr, hidhi, hidlo, DHALF, HID);
    gemm_mma_x3<false, false><<<gridD, blk, SMEM_BYTES>>>(hidhi, hidlo, wthi + 1 * WSLOT, wtlo + 1 * WSLOT, B[1], sbuf,    nullptr, nullptr, HID, DHALF);
    gemm_mma_x3<true,  true ><<<gridH, blk, SMEM_BYTES>>>(acthi, actlo, wthi + 2 * WSLOT, wtlo + 2 * WSLOT, B[2], nullptr, hidhi, hidlo, DHALF, HID);
    gemm_mma_x3<false, false><<<gridD, blk, SMEM_BYTES>>>(hidhi, hidlo, wthi + 3 * WSLOT, wtlo + 3 * WSLOT, B[3], tbuf,    nullptr, nullptr, HID, DHALF);
    ew_couple<<<BATCH, 256>>>(x, sbuf, tbuf, y, logdet, acthi, actlo, 0, 0, 0, 1);

    // phase 2
    gemm_mma_x3<true,  true ><<<gridH, blk, SMEM_BYTES>>>(acthi, actlo, wthi + 4 * WSLOT, wtlo + 4 * WSLOT, B[4], nullptr, hidhi, hidlo, DHALF, HID);
    gemm_mma_x3<false, false><<<gridD, blk, SMEM_BYTES>>>(hidhi, hidlo, wthi + 5 * WSLOT, wtlo + 5 * WSLOT, B[5], sbuf,    nullptr, nullptr, HID, DHALF);
    gemm_mma_x3<true,  true ><<<gridH, blk, SMEM_BYTES>>>(acthi, actlo, wthi + 6 * WSLOT, wtlo + 6 * WSLOT, B[6], nullptr, hidhi, hidlo, DHALF, HID);
    gemm_mma_x3<false, false><<<gridD, blk, SMEM_BYTES>>>(hidhi, hidlo, wthi + 7 * WSLOT, wtlo + 7 * WSLOT, B[7], tbuf,    nullptr, nullptr, HID, DHALF);
    ew_couple<<<BATCH, 256>>>(x, sbuf, tbuf, y, logdet, nullptr, nullptr, DHALF, DHALF, 1, 0);
}

// round 5
// speedup vs baseline: 1.0356x; 1.0356x over previous
#include <cuda_runtime.h>
#include <cuda_bf16.h>
#include <cstdint>
#include <math.h>

#define BATCH 8192
#define DHALF 1024
#define HID   4096
#define XCOLS 2048
#define WSLOT ((size_t)DHALF * HID)

// ---------------- scratch (device globals: allocation-free rule) -----------
__device__ __nv_bfloat16 g_act_hi[(size_t)BATCH * DHALF];
__device__ __nv_bfloat16 g_act_lo[(size_t)BATCH * DHALF];
__device__ __nv_bfloat16 g_hid_hi[(size_t)BATCH * HID];
__device__ __nv_bfloat16 g_hid_lo[(size_t)BATCH * HID];
__device__ __nv_bfloat16 g_wt_hi[8 * WSLOT];
__device__ __nv_bfloat16 g_wt_lo[8 * WSLOT];
__device__ float g_s[(size_t)BATCH * DHALF];
__device__ float g_t[(size_t)BATCH * DHALF];

// ---------------- helpers ----------------------------------------------
__device__ __forceinline__ uint32_t smem_u32(const void* p) {
    uint32_t a;
    asm("{ .reg .u64 t; cvta.to.shared.u64 t, %1; cvt.u32.u64 %0, t; }" : "=r"(a) : "l"(p));
    return a;
}
__device__ __forceinline__ void cp16(uint32_t s, const void* g) {
    asm volatile("cp.async.cg.shared.global [%0], [%1], 16;" :: "r"(s), "l"(g));
}
__device__ __forceinline__ void split_bf(float v, __nv_bfloat16& hi, __nv_bfloat16& lo) {
    hi = __float2bfloat16(v);
    lo = __float2bfloat16(v - __bfloat162float(hi));
}
__device__ __forceinline__ uint32_t pack_bf2(__nv_bfloat16 a, __nv_bfloat16 b) {
    __nv_bfloat162 t = __halves2bfloat162(a, b);
    return *reinterpret_cast<uint32_t*>(&t);
}
__device__ __forceinline__ void mma16816(float* d, const uint32_t* a, uint32_t b0, uint32_t b1) {
    asm volatile(
        "mma.sync.aligned.m16n8k16.row.col.f32.bf16.bf16.f32 "
        "{%0,%1,%2,%3}, {%4,%5,%6,%7}, {%8,%9}, {%0,%1,%2,%3};"
        : "+f"(d[0]), "+f"(d[1]), "+f"(d[2]), "+f"(d[3])
        : "r"(a[0]), "r"(a[1]), "r"(a[2]), "r"(a[3]), "r"(b0), "r"(b1));
}
__device__ __forceinline__ void ldsm4(uint32_t* r, uint32_t addr) {
    asm volatile("ldmatrix.sync.aligned.m8n8.x4.shared.b16 {%0,%1,%2,%3}, [%4];"
        : "=r"(r[0]), "=r"(r[1]), "=r"(r[2]), "=r"(r[3]) : "r"(addr));
}

// ---------------------------------------------------------------------------
// bf16x3 split GEMM, tuned for 2 CTAs/SM:
// Block 128x128, BK=32, 2 smem stages (80KB), 1 __syncthreads per chunk,
// 8 warps (2m x 4n), warp tile 64x32, ldmatrix fragments, pitch 80B.
// ---------------------------------------------------------------------------
#define BM 128
#define BN 128
#define BK 32
#define PITCH  80u
#define TILEB  (128u * PITCH)            // 10240 B per matrix tile
#define STAGEB (4u * TILEB)              // 40960
#define SMEM_BYTES (2u * STAGEB)         // 81920

template<bool RELU, bool BF16OUT>
__global__ __launch_bounds__(256, 2)
void gemm_mma_x3(const __nv_bfloat16* __restrict__ Ahi, const __nv_bfloat16* __restrict__ Alo,
                 const __nv_bfloat16* __restrict__ Bhi, const __nv_bfloat16* __restrict__ Blo,
                 const float* __restrict__ bias,
                 float* __restrict__ Cf,
                 __nv_bfloat16* __restrict__ Chi, __nv_bfloat16* __restrict__ Clo,
                 int K, int N)
{
    extern __shared__ char smem[];
    const uint32_t sb = smem_u32(smem);
    const int tid = threadIdx.x;
    const int wid = tid >> 5;
    const int lid = tid & 31;
    const int wm = wid & 1;
    const int wn = wid >> 1;
    const int mBase = blockIdx.y * BM;
    const int nBase = blockIdx.x * BN;

    // per-thread load mapping: 512 16B chunks per tile, 2 per thread per tile
    const int lr_a = tid >> 2;            // via i = tid + 256j below
    (void)lr_a;

    auto load_stage = [&](int stage, int k0) {
        const uint32_t st = sb + stage * STAGEB;
        #pragma unroll
        for (int j = 0; j < 2; ++j) {
            int i = tid + 256 * j;            // 0..511
            int r = i >> 2, c = i & 3;        // row, 16B chunk (row = 64B)
            uint32_t off = (uint32_t)r * PITCH + (uint32_t)c * 16u;
            size_t ga = (size_t)(mBase + r) * K + k0 + c * 8;
            size_t gb = (size_t)(nBase + r) * K + k0 + c * 8;
            cp16(st + off,             Ahi + ga);
            cp16(st + TILEB + off,     Alo + ga);
            cp16(st + 2 * TILEB + off, Bhi + gb);
            cp16(st + 3 * TILEB + off, Blo + gb);
        }
        asm volatile("cp.async.commit_group;" ::: "memory");
    };

    float acc[4][4][4];
    #pragma unroll
    for (int i = 0; i < 4; ++i)
        #pragma unroll
        for (int j = 0; j < 4; ++j)
            #pragma unroll
            for (int q = 0; q < 4; ++q) acc[i][j][q] = 0.f;

    const int NC = K / BK;
    load_stage(0, 0);                       // prefetch chunk 0

    const int lr16 = lid & 15;
    const uint32_t lcol = (uint32_t)(lid >> 4) * 16u;

    for (int c = 0; c < NC; ++c) {
        const int s = c & 1;
        asm volatile("cp.async.wait_group 0;" ::: "memory");
        __syncthreads();                    // data visible + stage s^1 free

        if (c + 1 < NC) load_stage(s ^ 1, (c + 1) * BK);

        const uint32_t st = sb + s * STAGEB;
        const uint32_t aAddr = st + (uint32_t)(wm * 64 + lr16) * PITCH + lcol;
        const uint32_t bAddr = st + 2 * TILEB + (uint32_t)(wn * 32 + lr16) * PITCH + lcol;

        #pragma unroll
        for (int kb = 0; kb < 2; ++kb) {
            const uint32_t cOff = (uint32_t)kb * 32u;
            uint32_t ah[4][4], al[4][4], bh[2][4], bl[2][4];
            #pragma unroll
            for (int mi = 0; mi < 4; ++mi) {
                ldsm4(ah[mi], aAddr + (uint32_t)mi * (16u * PITCH) + cOff);
                ldsm4(al[mi], aAddr + TILEB + (uint32_t)mi * (16u * PITCH) + cOff);
            }
            #pragma unroll
            for (int g = 0; g < 2; ++g) {
                ldsm4(bh[g], bAddr + (uint32_t)g * (16u * PITCH) + cOff);
                ldsm4(bl[g], bAddr + TILEB + (uint32_t)g * (16u * PITCH) + cOff);
            }
            #pragma unroll
            for (int mi = 0; mi < 4; ++mi)
                #pragma unroll
                for (int ni = 0; ni < 4; ++ni)
                    mma16816(acc[mi][ni], ah[mi], bh[ni >> 1][ni & 1], bh[ni >> 1][(ni & 1) + 2]);
            #pragma unroll
            for (int mi = 0; mi < 4; ++mi)
                #pragma unroll
                for (int ni = 0; ni < 4; ++ni)
                    mma16816(acc[mi][ni], ah[mi], bl[ni >> 1][ni & 1], bl[ni >> 1][(ni & 1) + 2]);
            #pragma unroll
            for (int mi = 0; mi < 4; ++mi)
                #pragma unroll
                for (int ni = 0; ni < 4; ++ni)
                    mma16816(acc[mi][ni], al[mi], bh[ni >> 1][ni & 1], bh[ni >> 1][(ni & 1) + 2]);
        }
    }

    // ---- epilogue ----
    const int lr = lid >> 2;
    const int q2 = (lid & 3) * 2;
    #pragma unroll
    for (int mi = 0; mi < 4; ++mi) {
        #pragma unroll
        for (int half = 0; half < 2; ++half) {
            const int m = mBase + wm * 64 + mi * 16 + lr + half * 8;
            #pragma unroll
            for (int ni = 0; ni < 4; ++ni) {
                const int n = nBase + wn * 32 + ni * 8 + q2;
                float v0 = acc[mi][ni][half * 2 + 0] + bias[n];
                float v1 = acc[mi][ni][half * 2 + 1] + bias[n + 1];
                if (RELU) { v0 = fmaxf(v0, 0.f); v1 = fmaxf(v1, 0.f); }
                if (BF16OUT) {
                    __nv_bfloat16 h0, h1, l0, l1;
                    split_bf(v0, h0, l0);
                    split_bf(v1, h1, l1);
                    *reinterpret_cast<uint32_t*>(&Chi[(size_t)m * N + n]) = pack_bf2(h0, h1);
                    *reinterpret_cast<uint32_t*>(&Clo[(size_t)m * N + n]) = pack_bf2(l0, l1);
                } else {
                    *reinterpret_cast<float2*>(&Cf[(size_t)m * N + n]) = make_float2(v0, v1);
                }
            }
        }
    }
}

// ---------------------------------------------------------------------------
// Fused weight converter: 8 matrices, one launch (blockIdx.z = matrix).
// ---------------------------------------------------------------------------
__global__ __launch_bounds__(256)
void convert_wT8(const float* __restrict__ W0, const float* __restrict__ W1,
                 const float* __restrict__ W2, const float* __restrict__ W3,
                 const float* __restrict__ W4, const float* __restrict__ W5,
                 const float* __restrict__ W6, const float* __restrict__ W7,
                 __nv_bfloat16* __restrict__ Thi, __nv_bfloat16* __restrict__ Tlo)
{
    const int z = blockIdx.z;
    const float* Ws[8] = {W0, W1, W2, W3, W4, W5, W6, W7};
    const float* W = Ws[z];
    const int K = (z & 1) ? HID : DHALF;
    const int N = (z & 1) ? DHALF : HID;
    const int n0 = (z & 1) ? blockIdx.y * 32 : blockIdx.x * 32;
    const int k0 = (z & 1) ? blockIdx.x * 32 : blockIdx.y * 32;
    __nv_bfloat16* thi = Thi + (size_t)z * WSLOT;
    __nv_bfloat16* tlo = Tlo + (size_t)z * WSLOT;

    __shared__ float t[32][33];
    const int tx = threadIdx.x & 31, ty = threadIdx.x >> 5;
    #pragma unroll
    for (int i = 0; i < 4; ++i)
        t[ty + i * 8][tx] = W[(size_t)(k0 + ty + i * 8) * N + n0 + tx];
    __syncthreads();
    #pragma unroll
    for (int i = 0; i < 4; ++i) {
        int n = n0 + ty + i * 8;
        float v = t[tx][ty + i * 8];
        __nv_bfloat16 hi, lo;
        split_bf(v, hi, lo);
        thi[(size_t)n * K + k0 + tx] = hi;
        tlo[(size_t)n * K + k0 + tx] = lo;
    }
}

__global__ __launch_bounds__(256)
void convert_act(const float* __restrict__ x,
                 __nv_bfloat16* __restrict__ hi, __nv_bfloat16* __restrict__ lo)
{
    const int m = blockIdx.x;
    const int j = threadIdx.x * 4;
    float4 v = *reinterpret_cast<const float4*>(&x[(size_t)m * XCOLS + DHALF + j]);
    __nv_bfloat16 h0, h1, h2, h3, l0, l1, l2, l3;
    split_bf(v.x, h0, l0); split_bf(v.y, h1, l1);
    split_bf(v.z, h2, l2); split_bf(v.w, h3, l3);
    *reinterpret_cast<uint2*>(&hi[(size_t)m * DHALF + j]) = make_uint2(pack_bf2(h0, h1), pack_bf2(h2, h3));
    *reinterpret_cast<uint2*>(&lo[(size_t)m * DHALF + j]) = make_uint2(pack_bf2(l0, l1), pack_bf2(l2, l3));
}

// ---------------------------------------------------------------------------
// Coupling epilogue
// ---------------------------------------------------------------------------
__global__ __launch_bounds__(256)
void ew_couple(const float* __restrict__ x,
               const float* __restrict__ spre,
               const float* __restrict__ tval,
               float* __restrict__ y,
               float* __restrict__ logdet,
               __nv_bfloat16* __restrict__ acthi, __nv_bfloat16* __restrict__ actlo,
               int xColOff, int yColOff, int addLogdet, int writeAct)
{
    const int m = blockIdx.x;
    const int j = threadIdx.x * 4;

    float4 sp = *reinterpret_cast<const float4*>(&spre[(size_t)m * DHALF + j]);
    float4 tv = *reinterpret_cast<const float4*>(&tval[(size_t)m * DHALF + j]);
    float4 xv = *reinterpret_cast<const float4*>(&x[(size_t)m * XCOLS + xColOff + j]);

    float s0 = tanhf(sp.x), s1 = tanhf(sp.y), s2 = tanhf(sp.z), s3 = tanhf(sp.w);

    float4 o;
    o.x = xv.x * expf(s0) + tv.x;
    o.y = xv.y * expf(s1) + tv.y;
    o.z = xv.z * expf(s2) + tv.z;
    o.w = xv.w * expf(s3) + tv.w;
    *reinterpret_cast<float4*>(&y[(size_t)m * XCOLS + yColOff + j]) = o;

    if (writeAct) {
        __nv_bfloat16 h0, h1, h2, h3, l0, l1, l2, l3;
        split_bf(o.x, h0, l0); split_bf(o.y, h1, l1);
        split_bf(o.z, h2, l2); split_bf(o.w, h3, l3);
        *reinterpret_cast<uint2*>(&acthi[(size_t)m * DHALF + j]) = make_uint2(pack_bf2(h0, h1), pack_bf2(h2, h3));
        *reinterpret_cast<uint2*>(&actlo[(size_t)m * DHALF + j]) = make_uint2(pack_bf2(l0, l1), pack_bf2(l2, l3));
    }

    float lsum = s0 + s1 + s2 + s3;
    #pragma unroll
    for (int off = 16; off > 0; off >>= 1)
        lsum += __shfl_xor_sync(0xFFFFFFFFu, lsum, off);

    __shared__ float wsum[8];
    if ((threadIdx.x & 31) == 0) wsum[threadIdx.x >> 5] = lsum;
    __syncthreads();
    if (threadIdx.x == 0) {
        float tot = 0.0f;
        #pragma unroll
        for (int w = 0; w < 8; ++w) tot += wsum[w];
        if (addLogdet) logdet[m] += tot;
        else           logdet[m]  = tot;
    }
}

// ---------------------------------------------------------------------------
extern "C" void kernel_launch(void* const* d_in, const int* in_sizes, int n_in,
                              void* d_out, int out_size)
{
    (void)in_sizes; (void)n_in; (void)out_size;

    const float* x = (const float*)d_in[0];
    const float* W[8] = { (const float*)d_in[1],  (const float*)d_in[3],
                          (const float*)d_in[5],  (const float*)d_in[7],
                          (const float*)d_in[9],  (const float*)d_in[11],
                          (const float*)d_in[13], (const float*)d_in[15] };
    const float* B[8] = { (const float*)d_in[2],  (const float*)d_in[4],
                          (const float*)d_in[6],  (const float*)d_in[8],
                          (const float*)d_in[10], (const float*)d_in[12],
                          (const float*)d_in[14], (const float*)d_in[16] };

    float* y      = (float*)d_out;
    float* logdet = y + (size_t)BATCH * XCOLS;

    __nv_bfloat16 *acthi, *actlo, *hidhi, *hidlo, *wthi, *wtlo;
    float *sbuf, *tbuf;
    cudaGetSymbolAddress((void**)&acthi, g_act_hi);
    cudaGetSymbolAddress((void**)&actlo, g_act_lo);
    cudaGetSymbolAddress((void**)&hidhi, g_hid_hi);
    cudaGetSymbolAddress((void**)&hidlo, g_hid_lo);
    cudaGetSymbolAddress((void**)&wthi,  g_wt_hi);
    cudaGetSymbolAddress((void**)&wtlo,  g_wt_lo);
    cudaGetSymbolAddress((void**)&sbuf,  g_s);
    cudaGetSymbolAddress((void**)&tbuf,  g_t);

    cudaFuncSetAttribute(gemm_mma_x3<true,  true >, cudaFuncAttributeMaxDynamicSharedMemorySize, SMEM_BYTES);
    cudaFuncSetAttribute(gemm_mma_x3<false, false>, cudaFuncAttributeMaxDynamicSharedMemorySize, SMEM_BYTES);

    convert_wT8<<<dim3(128, 32, 8), 256>>>(W[0], W[1], W[2], W[3], W[4], W[5], W[6], W[7], wthi, wtlo);
    convert_act<<<BATCH, 256>>>(x, acthi, actlo);

    dim3 blk(256);
    dim3 gridH(HID / BN,   BATCH / BM);
    dim3 gridD(DHALF / BN, BATCH / BM);

    // phase 1
    gemm_mma_x3<true,  true ><<<gridH, blk, SMEM_BYTES>>>(acthi, actlo, wthi + 0 * WSLOT, wtlo + 0 * WSLOT, B[0], nullptr, hidhi, hidlo, DHALF, HID);
    gemm_mma_x3<false, false><<<gridD, blk, SMEM_BYTES>>>(hidhi, hidlo, wthi + 1 * WSLOT, wtlo + 1 * WSLOT, B[1], sbuf,    nullptr, nullptr, HID, DHALF);
    gemm_mma_x3<true,  true ><<<gridH, blk, SMEM_BYTES>>>(acthi, actlo, wthi + 2 * WSLOT, wtlo + 2 * WSLOT, B[2], nullptr, hidhi, hidlo, DHALF, HID);
    gemm_mma_x3<false, false><<<gridD, blk, SMEM_BYTES>>>(hidhi, hidlo, wthi + 3 * WSLOT, wtlo + 3 * WSLOT, B[3], tbuf,    nullptr, nullptr, HID, DHALF);
    ew_couple<<<BATCH, 256>>>(x, sbuf, tbuf, y, logdet, acthi, actlo, 0, 0, 0, 1);

    // phase 2
    gemm_mma_x3<true,  true ><<<gridH, blk, SMEM_BYTES>>>(acthi, actlo, wthi + 4 * WSLOT, wtlo + 4 * WSLOT, B[4], nullptr, hidhi, hidlo, DHALF, HID);
    gemm_mma_x3<false, false><<<gridD, blk, SMEM_BYTES>>>(hidhi, hidlo, wthi + 5 * WSLOT, wtlo + 5 * WSLOT, B[5], sbuf,    nullptr, nullptr, HID, DHALF);
    gemm_mma_x3<true,  true ><<<gridH, blk, SMEM_BYTES>>>(acthi, actlo, wthi + 6 * WSLOT, wtlo + 6 * WSLOT, B[6], nullptr, hidhi, hidlo, DHALF, HID);
    gemm_mma_x3<false, false><<<gridD, blk, SMEM_BYTES>>>(hidhi, hidlo, wthi + 7 * WSLOT, wtlo + 7 * WSLOT, B[7], tbuf,    nullptr, nullptr, HID, DHALF);
    ew_couple<<<BATCH, 256>>>(x, sbuf, tbuf, y, logdet, nullptr, nullptr, DHALF, DHALF, 1, 0);
}

// round 6
// speedup vs baseline: 1.5668x; 1.5130x over previous
#include <cuda_runtime.h>
#include <cuda_fp16.h>
#include <cstdint>
#include <math.h>

#define BATCH 8192
#define DHALF 1024
#define HID   4096
#define XCOLS 2048
#define WSLOT ((size_t)DHALF * HID)

// ---------------- scratch (device globals: allocation-free rule) -----------
__device__ __half g_act[(size_t)BATCH * DHALF];
__device__ __half g_hid[(size_t)BATCH * HID];
__device__ __half g_wt_hi[8 * WSLOT];
__device__ __half g_wt_lo[8 * WSLOT];
__device__ float g_s[(size_t)BATCH * DHALF];
__device__ float g_t[(size_t)BATCH * DHALF];

// ---------------- helpers ----------------------------------------------
__device__ __forceinline__ uint32_t smem_u32(const void* p) {
    uint32_t a;
    asm("{ .reg .u64 t; cvta.to.shared.u64 t, %1; cvt.u32.u64 %0, t; }" : "=r"(a) : "l"(p));
    return a;
}
__device__ __forceinline__ void cp16(uint32_t s, const void* g) {
    asm volatile("cp.async.cg.shared.global [%0], [%1], 16;" :: "r"(s), "l"(g));
}
__device__ __forceinline__ uint32_t pack_h2(__half a, __half b) {
    __half2 t = __halves2half2(a, b);
    return *reinterpret_cast<uint32_t*>(&t);
}
__device__ __forceinline__ void mma16816(float* d, const uint32_t* a, uint32_t b0, uint32_t b1) {
    asm volatile(
        "mma.sync.aligned.m16n8k16.row.col.f32.f16.f16.f32 "
        "{%0,%1,%2,%3}, {%4,%5,%6,%7}, {%8,%9}, {%0,%1,%2,%3};"
        : "+f"(d[0]), "+f"(d[1]), "+f"(d[2]), "+f"(d[3])
        : "r"(a[0]), "r"(a[1]), "r"(a[2]), "r"(a[3]), "r"(b0), "r"(b1));
}
__device__ __forceinline__ void ldsm4(uint32_t* r, uint32_t addr) {
    asm volatile("ldmatrix.sync.aligned.m8n8.x4.shared.b16 {%0,%1,%2,%3}, [%4];"
        : "=r"(r[0]), "=r"(r[1]), "=r"(r[2]), "=r"(r[3]) : "r"(addr));
}

// ---------------------------------------------------------------------------
// fp16 2-pass GEMM: C = A @ (Whi + Wlo)^T + bias, A fp16, W split fp16 hi/lo.
// Block 128x128, BK=32, 3 smem stages (A, Bhi, Blo; 92KB), 2 CTAs/SM,
// 8 warps (2m x 4n), warp tile 64x32, ldmatrix, pitch 80B.
// ---------------------------------------------------------------------------
#define BM 128
#define BN 128
#define BK 32
#define STAGES 3
#define PITCH  80u
#define TILEB  (128u * PITCH)            // 10240 B per tile
#define STAGEB (3u * TILEB)              // A, Bhi, Blo = 30720
#define SMEM_BYTES (STAGES * STAGEB)     // 92160

template<bool RELU, bool F16OUT>
__global__ __launch_bounds__(256, 2)
void gemm_fp16x2(const __half* __restrict__ A,
                 const __half* __restrict__ Bhi, const __half* __restrict__ Blo,
                 const float* __restrict__ bias,
                 float* __restrict__ Cf, __half* __restrict__ Ch,
                 int K, int N)
{
    extern __shared__ char smem[];
    const uint32_t sb = smem_u32(smem);
    const int tid = threadIdx.x;
    const int wid = tid >> 5;
    const int lid = tid & 31;
    const int wm = wid & 1;
    const int wn = wid >> 1;
    const int mBase = blockIdx.y * BM;
    const int nBase = blockIdx.x * BN;

    auto load_stage = [&](int stage, int k0) {
        const uint32_t st = sb + stage * STAGEB;
        #pragma unroll
        for (int j = 0; j < 2; ++j) {
            int i = tid + 256 * j;            // 0..511
            int r = i >> 2, c = i & 3;
            uint32_t off = (uint32_t)r * PITCH + (uint32_t)c * 16u;
            size_t ga = (size_t)(mBase + r) * K + k0 + c * 8;
            size_t gb = (size_t)(nBase + r) * K + k0 + c * 8;
            cp16(st + off,             A   + ga);
            cp16(st + TILEB + off,     Bhi + gb);
            cp16(st + 2 * TILEB + off, Blo + gb);
        }
        asm volatile("cp.async.commit_group;" ::: "memory");
    };

    float acc[4][4][4];
    #pragma unroll
    for (int i = 0; i < 4; ++i)
        #pragma unroll
        for (int j = 0; j < 4; ++j)
            #pragma unroll
            for (int q = 0; q < 4; ++q) acc[i][j][q] = 0.f;

    const int NC = K / BK;
    load_stage(0, 0);
    load_stage(1, BK);

    const int lr16 = lid & 15;
    const uint32_t lcol = (uint32_t)(lid >> 4) * 16u;

    for (int c = 0; c < NC; ++c) {
        const int s = c % STAGES;
        asm volatile("cp.async.wait_group 1;" ::: "memory");
        __syncthreads();

        if (c + 2 < NC) load_stage((c + 2) % STAGES, (c + 2) * BK);

        const uint32_t st = sb + s * STAGEB;
        const uint32_t aAddr = st + (uint32_t)(wm * 64 + lr16) * PITCH + lcol;
        const uint32_t bAddr = st + TILEB + (uint32_t)(wn * 32 + lr16) * PITCH + lcol;

        #pragma unroll
        for (int kb = 0; kb < 2; ++kb) {
            const uint32_t cOff = (uint32_t)kb * 32u;
            uint32_t ah[4][4], bh[2][4], bl[2][4];
            #pragma unroll
            for (int mi = 0; mi < 4; ++mi)
                ldsm4(ah[mi], aAddr + (uint32_t)mi * (16u * PITCH) + cOff);
            #pragma unroll
            for (int g = 0; g < 2; ++g) {
                ldsm4(bh[g], bAddr + (uint32_t)g * (16u * PITCH) + cOff);
                ldsm4(bl[g], bAddr + TILEB + (uint32_t)g * (16u * PITCH) + cOff);
            }
            #pragma unroll
            for (int mi = 0; mi < 4; ++mi)
                #pragma unroll
                for (int ni = 0; ni < 4; ++ni)
                    mma16816(acc[mi][ni], ah[mi], bh[ni >> 1][ni & 1], bh[ni >> 1][(ni & 1) + 2]);
            #pragma unroll
            for (int mi = 0; mi < 4; ++mi)
                #pragma unroll
                for (int ni = 0; ni < 4; ++ni)
                    mma16816(acc[mi][ni], ah[mi], bl[ni >> 1][ni & 1], bl[ni >> 1][(ni & 1) + 2]);
        }
    }

    // ---- epilogue ----
    const int lr = lid >> 2;
    const int q2 = (lid & 3) * 2;
    #pragma unroll
    for (int mi = 0; mi < 4; ++mi) {
        #pragma unroll
        for (int half = 0; half < 2; ++half) {
            const int m = mBase + wm * 64 + mi * 16 + lr + half * 8;
            #pragma unroll
            for (int ni = 0; ni < 4; ++ni) {
                const int n = nBase + wn * 32 + ni * 8 + q2;
                float v0 = acc[mi][ni][half * 2 + 0] + bias[n];
                float v1 = acc[mi][ni][half * 2 + 1] + bias[n + 1];
                if (RELU) { v0 = fmaxf(v0, 0.f); v1 = fmaxf(v1, 0.f); }
                if (F16OUT) {
                    *reinterpret_cast<uint32_t*>(&Ch[(size_t)m * N + n]) =
                        pack_h2(__float2half(v0), __float2half(v1));
                } else {
                    *reinterpret_cast<float2*>(&Cf[(size_t)m * N + n]) = make_float2(v0, v1);
                }
            }
        }
    }
}

// ---------------------------------------------------------------------------
// Fused weight converter: W[K,N] fp32 -> WT[N,K] fp16 hi/lo, 8 matrices.
// ---------------------------------------------------------------------------
__global__ __launch_bounds__(256)
void convert_wT8(const float* __restrict__ W0, const float* __restrict__ W1,
                 const float* __restrict__ W2, const float* __restrict__ W3,
                 const float* __restrict__ W4, const float* __restrict__ W5,
                 const float* __restrict__ W6, const float* __restrict__ W7,
                 __half* __restrict__ Thi, __half* __restrict__ Tlo)
{
    const int z = blockIdx.z;
    const float* Ws[8] = {W0, W1, W2, W3, W4, W5, W6, W7};
    const float* W = Ws[z];
    const int K = (z & 1) ? HID : DHALF;
    const int N = (z & 1) ? DHALF : HID;
    const int n0 = (z & 1) ? blockIdx.y * 32 : blockIdx.x * 32;
    const int k0 = (z & 1) ? blockIdx.x * 32 : blockIdx.y * 32;
    __half* thi = Thi + (size_t)z * WSLOT;
    __half* tlo = Tlo + (size_t)z * WSLOT;

    __shared__ float t[32][33];
    const int tx = threadIdx.x & 31, ty = threadIdx.x >> 5;
    #pragma unroll
    for (int i = 0; i < 4; ++i)
        t[ty + i * 8][tx] = W[(size_t)(k0 + ty + i * 8) * N + n0 + tx];
    __syncthreads();
    #pragma unroll
    for (int i = 0; i < 4; ++i) {
        int n = n0 + ty + i * 8;
        float v = t[tx][ty + i * 8];
        __half hi = __float2half(v);
        __half lo = __float2half(v - __half2float(hi));
        thi[(size_t)n * K + k0 + tx] = hi;
        tlo[(size_t)n * K + k0 + tx] = lo;
    }
}

__global__ __launch_bounds__(256)
void convert_act(const float* __restrict__ x, __half* __restrict__ a)
{
    const int m = blockIdx.x;
    const int j = threadIdx.x * 4;
    float4 v = *reinterpret_cast<const float4*>(&x[(size_t)m * XCOLS + DHALF + j]);
    uint2 o = make_uint2(pack_h2(__float2half(v.x), __float2half(v.y)),
                         pack_h2(__float2half(v.z), __float2half(v.w)));
    *reinterpret_cast<uint2*>(&a[(size_t)m * DHALF + j]) = o;
}

// ---------------------------------------------------------------------------
// Coupling epilogue: y = x_in * exp(tanh(spre)) + tval; logdet; opt fp16 act.
// ---------------------------------------------------------------------------
__global__ __launch_bounds__(256)
void ew_couple(const float* __restrict__ x,
               const float* __restrict__ spre,
               const float* __restrict__ tval,
               float* __restrict__ y,
               float* __restrict__ logdet,
               __half* __restrict__ act,
               int xColOff, int yColOff, int addLogdet, int writeAct)
{
    const int m = blockIdx.x;
    const int j = threadIdx.x * 4;

    float4 sp = *reinterpret_cast<const float4*>(&spre[(size_t)m * DHALF + j]);
    float4 tv = *reinterpret_cast<const float4*>(&tval[(size_t)m * DHALF + j]);
    float4 xv = *reinterpret_cast<const float4*>(&x[(size_t)m * XCOLS + xColOff + j]);

    float s0 = tanhf(sp.x), s1 = tanhf(sp.y), s2 = tanhf(sp.z), s3 = tanhf(sp.w);

    float4 o;
    o.x = xv.x * expf(s0) + tv.x;
    o.y = xv.y * expf(s1) + tv.y;
    o.z = xv.z * expf(s2) + tv.z;
    o.w = xv.w * expf(s3) + tv.w;
    *reinterpret_cast<float4*>(&y[(size_t)m * XCOLS + yColOff + j]) = o;

    if (writeAct) {
        uint2 av = make_uint2(pack_h2(__float2half(o.x), __float2half(o.y)),
                              pack_h2(__float2half(o.z), __float2half(o.w)));
        *reinterpret_cast<uint2*>(&act[(size_t)m * DHALF + j]) = av;
    }

    float lsum = s0 + s1 + s2 + s3;
    #pragma unroll
    for (int off = 16; off > 0; off >>= 1)
        lsum += __shfl_xor_sync(0xFFFFFFFFu, lsum, off);

    __shared__ float wsum[8];
    if ((threadIdx.x & 31) == 0) wsum[threadIdx.x >> 5] = lsum;
    __syncthreads();
    if (threadIdx.x == 0) {
        float tot = 0.0f;
        #pragma unroll
        for (int w = 0; w < 8; ++w) tot += wsum[w];
        if (addLogdet) logdet[m] += tot;
        else           logdet[m]  = tot;
    }
}

// ---------------------------------------------------------------------------
extern "C" void kernel_launch(void* const* d_in, const int* in_sizes, int n_in,
                              void* d_out, int out_size)
{
    (void)in_sizes; (void)n_in; (void)out_size;

    const float* x = (const float*)d_in[0];
    const float* W[8] = { (const float*)d_in[1],  (const float*)d_in[3],
                          (const float*)d_in[5],  (const float*)d_in[7],
                          (const float*)d_in[9],  (const float*)d_in[11],
                          (const float*)d_in[13], (const float*)d_in[15] };
    const float* B[8] = { (const float*)d_in[2],  (const float*)d_in[4],
                          (const float*)d_in[6],  (const float*)d_in[8],
                          (const float*)d_in[10], (const float*)d_in[12],
                          (const float*)d_in[14], (const float*)d_in[16] };

    float* y      = (float*)d_out;
    float* logdet = y + (size_t)BATCH * XCOLS;

    __half *act, *hid, *wthi, *wtlo;
    float *sbuf, *tbuf;
    cudaGetSymbolAddress((void**)&act,  g_act);
    cudaGetSymbolAddress((void**)&hid,  g_hid);
    cudaGetSymbolAddress((void**)&wthi, g_wt_hi);
    cudaGetSymbolAddress((void**)&wtlo, g_wt_lo);
    cudaGetSymbolAddress((void**)&sbuf, g_s);
    cudaGetSymbolAddress((void**)&tbuf, g_t);

    cudaFuncSetAttribute(gemm_fp16x2<true,  true >, cudaFuncAttributeMaxDynamicSharedMemorySize, SMEM_BYTES);
    cudaFuncSetAttribute(gemm_fp16x2<false, false>, cudaFuncAttributeMaxDynamicSharedMemorySize, SMEM_BYTES);

    convert_wT8<<<dim3(128, 32, 8), 256>>>(W[0], W[1], W[2], W[3], W[4], W[5], W[6], W[7], wthi, wtlo);
    convert_act<<<BATCH, 256>>>(x, act);

    dim3 blk(256);
    dim3 gridH(HID / BN,   BATCH / BM);
    dim3 gridD(DHALF / BN, BATCH / BM);

    // phase 1
    gemm_fp16x2<true,  true ><<<gridH, blk, SMEM_BYTES>>>(act, wthi + 0 * WSLOT, wtlo + 0 * WSLOT, B[0], nullptr, hid, DHALF, HID);
    gemm_fp16x2<false, false><<<gridD, blk, SMEM_BYTES>>>(hid, wthi + 1 * WSLOT, wtlo + 1 * WSLOT, B[1], sbuf, nullptr, HID, DHALF);
    gemm_fp16x2<true,  true ><<<gridH, blk, SMEM_BYTES>>>(act, wthi + 2 * WSLOT, wtlo + 2 * WSLOT, B[2], nullptr, hid, DHALF, HID);
    gemm_fp16x2<false, false><<<gridD, blk, SMEM_BYTES>>>(hid, wthi + 3 * WSLOT, wtlo + 3 * WSLOT, B[3], tbuf, nullptr, HID, DHALF);
    ew_couple<<<BATCH, 256>>>(x, sbuf, tbuf, y, logdet, act, 0, 0, 0, 1);

    // phase 2
    gemm_fp16x2<true,  true ><<<gridH, blk, SMEM_BYTES>>>(act, wthi + 4 * WSLOT, wtlo + 4 * WSLOT, B[4], nullptr, hid, DHALF, HID);
    gemm_fp16x2<false, false><<<gridD, blk, SMEM_BYTES>>>(hid, wthi + 5 * WSLOT, wtlo + 5 * WSLOT, B[5], sbuf, nullptr, HID, DHALF);
    gemm_fp16x2<true,  true ><<<gridH, blk, SMEM_BYTES>>>(act, wthi + 6 * WSLOT, wtlo + 6 * WSLOT, B[6], nullptr, hid, DHALF, HID);
    gemm_fp16x2<false, false><<<gridD, blk, SMEM_BYTES>>>(hid, wthi + 7 * WSLOT, wtlo + 7 * WSLOT, B[7], tbuf, nullptr, HID, DHALF);
    ew_couple<<<BATCH, 256>>>(x, sbuf, tbuf, y, logdet, nullptr, DHALF, DHALF, 1, 0);
}

// round 7
// speedup vs baseline: 2.5622x; 1.6353x over previous
#include <cuda_runtime.h>
#include <cuda_fp16.h>
#include <cstdint>
#include <math.h>

#define BATCH 8192
#define DHALF 1024
#define HID   4096
#define XCOLS 2048
#define WSLOT ((size_t)DHALF * HID)

// ---------------- scratch (device globals: allocation-free rule) -----------
__device__ __half g_act[(size_t)BATCH * DHALF];
__device__ __half g_hid[(size_t)BATCH * HID];
__device__ __half g_wt[8 * WSLOT];
__device__ float g_s[(size_t)BATCH * DHALF];
__device__ float g_t[(size_t)BATCH * DHALF];

// ---------------- helpers ----------------------------------------------
__device__ __forceinline__ uint32_t smem_u32(const void* p) {
    uint32_t a;
    asm("{ .reg .u64 t; cvta.to.shared.u64 t, %1; cvt.u32.u64 %0, t; }" : "=r"(a) : "l"(p));
    return a;
}
__device__ __forceinline__ void cp16(uint32_t s, const void* g) {
    asm volatile("cp.async.cg.shared.global [%0], [%1], 16;" :: "r"(s), "l"(g));
}
__device__ __forceinline__ uint32_t pack_h2(__half a, __half b) {
    __half2 t = __halves2half2(a, b);
    return *reinterpret_cast<uint32_t*>(&t);
}
__device__ __forceinline__ void mma16816(float* d, const uint32_t* a, uint32_t b0, uint32_t b1) {
    asm volatile(
        "mma.sync.aligned.m16n8k16.row.col.f32.f16.f16.f32 "
        "{%0,%1,%2,%3}, {%4,%5,%6,%7}, {%8,%9}, {%0,%1,%2,%3};"
        : "+f"(d[0]), "+f"(d[1]), "+f"(d[2]), "+f"(d[3])
        : "r"(a[0]), "r"(a[1]), "r"(a[2]), "r"(a[3]), "r"(b0), "r"(b1));
}
__device__ __forceinline__ void ldsm4(uint32_t* r, uint32_t addr) {
    asm volatile("ldmatrix.sync.aligned.m8n8.x4.shared.b16 {%0,%1,%2,%3}, [%4];"
        : "=r"(r[0]), "=r"(r[1]), "=r"(r[2]), "=r"(r[3]) : "r"(addr));
}

// ---------------------------------------------------------------------------
// Single-pass fp16 GEMM: C = A @ W^T + bias.
// Block 128x128, BK=32, 4 smem stages (80KB), 2 CTAs/SM,
// 8 warps (2m x 4n), warp tile 64x32, ldmatrix, pitch 80B.
// ---------------------------------------------------------------------------
#define BM 128
#define BN 128
#define BK 32
#define STAGES 4
#define PITCH  80u
#define TILEB  (128u * PITCH)            // 10240 B per tile
#define STAGEB (2u * TILEB)              // A, B = 20480
#define SMEM_BYTES (STAGES * STAGEB)     // 81920

template<bool RELU, bool F16OUT>
__global__ __launch_bounds__(256, 2)
void gemm_fp16(const __half* __restrict__ A,
               const __half* __restrict__ B,
               const float* __restrict__ bias,
               float* __restrict__ Cf, __half* __restrict__ Ch,
               int K, int N)
{
    extern __shared__ char smem[];
    const uint32_t sb = smem_u32(smem);
    const int tid = threadIdx.x;
    const int wid = tid >> 5;
    const int lid = tid & 31;
    const int wm = wid & 1;
    const int wn = wid >> 1;
    const int mBase = blockIdx.y * BM;
    const int nBase = blockIdx.x * BN;

    auto load_stage = [&](int stage, int k0) {
        const uint32_t st = sb + stage * STAGEB;
        #pragma unroll
        for (int j = 0; j < 2; ++j) {
            int i = tid + 256 * j;            // 0..511
            int r = i >> 2, c = i & 3;
            uint32_t off = (uint32_t)r * PITCH + (uint32_t)c * 16u;
            size_t ga = (size_t)(mBase + r) * K + k0 + c * 8;
            size_t gb = (size_t)(nBase + r) * K + k0 + c * 8;
            cp16(st + off,         A + ga);
            cp16(st + TILEB + off, B + gb);
        }
        asm volatile("cp.async.commit_group;" ::: "memory");
    };

    float acc[4][4][4];
    #pragma unroll
    for (int i = 0; i < 4; ++i)
        #pragma unroll
        for (int j = 0; j < 4; ++j)
            #pragma unroll
            for (int q = 0; q < 4; ++q) acc[i][j][q] = 0.f;

    const int NC = K / BK;
    load_stage(0, 0);
    load_stage(1, BK);
    load_stage(2, 2 * BK);

    const int lr16 = lid & 15;
    const uint32_t lcol = (uint32_t)(lid >> 4) * 16u;

    for (int c = 0; c < NC; ++c) {
        const int s = c % STAGES;
        asm volatile("cp.async.wait_group 2;" ::: "memory");
        __syncthreads();

        if (c + 3 < NC) load_stage((c + 3) % STAGES, (c + 3) * BK);

        const uint32_t st = sb + s * STAGEB;
        const uint32_t aAddr = st + (uint32_t)(wm * 64 + lr16) * PITCH + lcol;
        const uint32_t bAddr = st + TILEB + (uint32_t)(wn * 32 + lr16) * PITCH + lcol;

        #pragma unroll
        for (int kb = 0; kb < 2; ++kb) {
            const uint32_t cOff = (uint32_t)kb * 32u;
            uint32_t ah[4][4], bh[2][4];
            #pragma unroll
            for (int mi = 0; mi < 4; ++mi)
                ldsm4(ah[mi], aAddr + (uint32_t)mi * (16u * PITCH) + cOff);
            #pragma unroll
            for (int g = 0; g < 2; ++g)
                ldsm4(bh[g], bAddr + (uint32_t)g * (16u * PITCH) + cOff);
            #pragma unroll
            for (int mi = 0; mi < 4; ++mi)
                #pragma unroll
                for (int ni = 0; ni < 4; ++ni)
                    mma16816(acc[mi][ni], ah[mi], bh[ni >> 1][ni & 1], bh[ni >> 1][(ni & 1) + 2]);
        }
    }

    // ---- epilogue ----
    const int lr = lid >> 2;
    const int q2 = (lid & 3) * 2;
    #pragma unroll
    for (int mi = 0; mi < 4; ++mi) {
        #pragma unroll
        for (int half = 0; half < 2; ++half) {
            const int m = mBase + wm * 64 + mi * 16 + lr + half * 8;
            #pragma unroll
            for (int ni = 0; ni < 4; ++ni) {
                const int n = nBase + wn * 32 + ni * 8 + q2;
                float v0 = acc[mi][ni][half * 2 + 0] + bias[n];
                float v1 = acc[mi][ni][half * 2 + 1] + bias[n + 1];
                if (RELU) { v0 = fmaxf(v0, 0.f); v1 = fmaxf(v1, 0.f); }
                if (F16OUT) {
                    *reinterpret_cast<uint32_t*>(&Ch[(size_t)m * N + n]) =
                        pack_h2(__float2half(v0), __float2half(v1));
                } else {
                    *reinterpret_cast<float2*>(&Cf[(size_t)m * N + n]) = make_float2(v0, v1);
                }
            }
        }
    }
}

// ---------------------------------------------------------------------------
// Fused weight converter: W[K,N] fp32 -> WT[N,K] fp16, 8 matrices, one launch.
// ---------------------------------------------------------------------------
__global__ __launch_bounds__(256)
void convert_wT8(const float* __restrict__ W0, const float* __restrict__ W1,
                 const float* __restrict__ W2, const float* __restrict__ W3,
                 const float* __restrict__ W4, const float* __restrict__ W5,
                 const float* __restrict__ W6, const float* __restrict__ W7,
                 __half* __restrict__ T)
{
    const int z = blockIdx.z;
    const float* Ws[8] = {W0, W1, W2, W3, W4, W5, W6, W7};
    const float* W = Ws[z];
    const int K = (z & 1) ? HID : DHALF;
    const int N = (z & 1) ? DHALF : HID;
    const int n0 = (z & 1) ? blockIdx.y * 32 : blockIdx.x * 32;
    const int k0 = (z & 1) ? blockIdx.x * 32 : blockIdx.y * 32;
    __half* t_out = T + (size_t)z * WSLOT;

    __shared__ float t[32][33];
    const int tx = threadIdx.x & 31, ty = threadIdx.x >> 5;
    #pragma unroll
    for (int i = 0; i < 4; ++i)
        t[ty + i * 8][tx] = W[(size_t)(k0 + ty + i * 8) * N + n0 + tx];
    __syncthreads();
    #pragma unroll
    for (int i = 0; i < 4; ++i) {
        int n = n0 + ty + i * 8;
        t_out[(size_t)n * K + k0 + tx] = __float2half(t[tx][ty + i * 8]);
    }
}

__global__ __launch_bounds__(256)
void convert_act(const float* __restrict__ x, __half* __restrict__ a)
{
    const int m = blockIdx.x;
    const int j = threadIdx.x * 4;
    float4 v = *reinterpret_cast<const float4*>(&x[(size_t)m * XCOLS + DHALF + j]);
    uint2 o = make_uint2(pack_h2(__float2half(v.x), __float2half(v.y)),
                         pack_h2(__float2half(v.z), __float2half(v.w)));
    *reinterpret_cast<uint2*>(&a[(size_t)m * DHALF + j]) = o;
}

// ---------------------------------------------------------------------------
// Coupling epilogue: y = x_in * exp(tanh(spre)) + tval; logdet; opt fp16 act.
// ---------------------------------------------------------------------------
__global__ __launch_bounds__(256)
void ew_couple(const float* __restrict__ x,
               const float* __restrict__ spre,
               const float* __restrict__ tval,
               float* __restrict__ y,
               float* __restrict__ logdet,
               __half* __restrict__ act,
               int xColOff, int yColOff, int addLogdet, int writeAct)
{
    const int m = blockIdx.x;
    const int j = threadIdx.x * 4;

    float4 sp = *reinterpret_cast<const float4*>(&spre[(size_t)m * DHALF + j]);
    float4 tv = *reinterpret_cast<const float4*>(&tval[(size_t)m * DHALF + j]);
    float4 xv = *reinterpret_cast<const float4*>(&x[(size_t)m * XCOLS + xColOff + j]);

    float s0 = tanhf(sp.x), s1 = tanhf(sp.y), s2 = tanhf(sp.z), s3 = tanhf(sp.w);

    float4 o;
    o.x = xv.x * expf(s0) + tv.x;
    o.y = xv.y * expf(s1) + tv.y;
    o.z = xv.z * expf(s2) + tv.z;
    o.w = xv.w * expf(s3) + tv.w;
    *reinterpret_cast<float4*>(&y[(size_t)m * XCOLS + yColOff + j]) = o;

    if (writeAct) {
        uint2 av = make_uint2(pack_h2(__float2half(o.x), __float2half(o.y)),
                              pack_h2(__float2half(o.z), __float2half(o.w)));
        *reinterpret_cast<uint2*>(&act[(size_t)m * DHALF + j]) = av;
    }

    float lsum = s0 + s1 + s2 + s3;
    #pragma unroll
    for (int off = 16; off > 0; off >>= 1)
        lsum += __shfl_xor_sync(0xFFFFFFFFu, lsum, off);

    __shared__ float wsum[8];
    if ((threadIdx.x & 31) == 0) wsum[threadIdx.x >> 5] = lsum;
    __syncthreads();
    if (threadIdx.x == 0) {
        float tot = 0.0f;
        #pragma unroll
        for (int w = 0; w < 8; ++w) tot += wsum[w];
        if (addLogdet) logdet[m] += tot;
        else           logdet[m]  = tot;
    }
}

// ---------------------------------------------------------------------------
extern "C" void kernel_launch(void* const* d_in, const int* in_sizes, int n_in,
                              void* d_out, int out_size)
{
    (void)in_sizes; (void)n_in; (void)out_size;

    const float* x = (const float*)d_in[0];
    const float* W[8] = { (const float*)d_in[1],  (const float*)d_in[3],
                          (const float*)d_in[5],  (const float*)d_in[7],
                          (const float*)d_in[9],  (const float*)d_in[11],
                          (const float*)d_in[13], (const float*)d_in[15] };
    const float* B[8] = { (const float*)d_in[2],  (const float*)d_in[4],
                          (const float*)d_in[6],  (const float*)d_in[8],
                          (const float*)d_in[10], (const float*)d_in[12],
                          (const float*)d_in[14], (const float*)d_in[16] };

    float* y      = (float*)d_out;
    float* logdet = y + (size_t)BATCH * XCOLS;

    __half *act, *hid, *wt;
    float *sbuf, *tbuf;
    cudaGetSymbolAddress((void**)&act, g_act);
    cudaGetSymbolAddress((void**)&hid, g_hid);
    cudaGetSymbolAddress((void**)&wt,  g_wt);
    cudaGetSymbolAddress((void**)&sbuf, g_s);
    cudaGetSymbolAddress((void**)&tbuf, g_t);

    cudaFuncSetAttribute(gemm_fp16<true,  true >, cudaFuncAttributeMaxDynamicSharedMemorySize, SMEM_BYTES);
    cudaFuncSetAttribute(gemm_fp16<false, false>, cudaFuncAttributeMaxDynamicSharedMemorySize, SMEM_BYTES);

    convert_wT8<<<dim3(128, 32, 8), 256>>>(W[0], W[1], W[2], W[3], W[4], W[5], W[6], W[7], wt);
    convert_act<<<BATCH, 256>>>(x, act);

    dim3 blk(256);
    dim3 gridH(HID / BN,   BATCH / BM);
    dim3 gridD(DHALF / BN, BATCH / BM);

    // phase 1
    gemm_fp16<true,  true ><<<gridH, blk, SMEM_BYTES>>>(act, wt + 0 * WSLOT, B[0], nullptr, hid, DHALF, HID);
    gemm_fp16<false, false><<<gridD, blk, SMEM_BYTES>>>(hid, wt + 1 * WSLOT, B[1], sbuf, nullptr, HID, DHALF);
    gemm_fp16<true,  true ><<<gridH, blk, SMEM_BYTES>>>(act, wt + 2 * WSLOT, B[2], nullptr, hid, DHALF, HID);
    gemm_fp16<false, false><<<gridD, blk, SMEM_BYTES>>>(hid, wt + 3 * WSLOT, B[3], tbuf, nullptr, HID, DHALF);
    ew_couple<<<BATCH, 256>>>(x, sbuf, tbuf, y, logdet, act, 0, 0, 0, 1);

    // phase 2
    gemm_fp16<true,  true ><<<gridH, blk, SMEM_BYTES>>>(act, wt + 4 * WSLOT, B[4], nullptr, hid, DHALF, HID);
    gemm_fp16<false, false><<<gridD, blk, SMEM_BYTES>>>(hid, wt + 5 * WSLOT, B[5], sbuf, nullptr, HID, DHALF);
    gemm_fp16<true,  true ><<<gridH, blk, SMEM_BYTES>>>(act, wt + 6 * WSLOT, B[6], nullptr, hid, DHALF, HID);
    gemm_fp16<false, false><<<gridD, blk, SMEM_BYTES>>>(hid, wt + 7 * WSLOT, B[7], tbuf, nullptr, HID, DHALF);
    ew_couple<<<BATCH, 256>>>(x, sbuf, tbuf, y, logdet, nullptr, DHALF, DHALF, 1, 0);
}

// round 8
// speedup vs baseline: 2.9128x; 1.1368x over previous
#include <cuda_runtime.h>
#include <cuda_fp16.h>
#include <cstdint>
#include <math.h>

#define BATCH 8192
#define DHALF 1024
#define HID   4096
#define XCOLS 2048
#define WSLOT ((size_t)DHALF * HID)

// ---------------- scratch (device globals: allocation-free rule) -----------
__device__ __half g_act[(size_t)BATCH * DHALF];
__device__ __half g_hid[(size_t)BATCH * HID];
__device__ __half g_wt[8 * WSLOT];
__device__ float g_s[(size_t)BATCH * DHALF];
__device__ float g_t[(size_t)BATCH * DHALF];

// ---------------- helpers ----------------------------------------------
__device__ __forceinline__ uint32_t smem_u32(const void* p) {
    uint32_t a;
    asm("{ .reg .u64 t; cvta.to.shared.u64 t, %1; cvt.u32.u64 %0, t; }" : "=r"(a) : "l"(p));
    return a;
}
__device__ __forceinline__ void cp16(uint32_t s, const void* g) {
    asm volatile("cp.async.cg.shared.global [%0], [%1], 16;" :: "r"(s), "l"(g));
}
__device__ __forceinline__ uint32_t pack_h2(__half a, __half b) {
    __half2 t = __halves2half2(a, b);
    return *reinterpret_cast<uint32_t*>(&t);
}
__device__ __forceinline__ void mma16816(float* d, const uint32_t* a, uint32_t b0, uint32_t b1) {
    asm volatile(
        "mma.sync.aligned.m16n8k16.row.col.f32.f16.f16.f32 "
        "{%0,%1,%2,%3}, {%4,%5,%6,%7}, {%8,%9}, {%0,%1,%2,%3};"
        : "+f"(d[0]), "+f"(d[1]), "+f"(d[2]), "+f"(d[3])
        : "r"(a[0]), "r"(a[1]), "r"(a[2]), "r"(a[3]), "r"(b0), "r"(b1));
}
__device__ __forceinline__ void ldsm4(uint32_t* r, uint32_t addr) {
    asm volatile("ldmatrix.sync.aligned.m8n8.x4.shared.b16 {%0,%1,%2,%3}, [%4];"
        : "=r"(r[0]), "=r"(r[1]), "=r"(r[2]), "=r"(r[3]) : "r"(addr));
}

// ---------------------------------------------------------------------------
// Single-pass fp16 GEMM: C = A @ W^T + bias.
// Block 128x128, BK=64, 3 smem stages (110.6KB), 2 CTAs/SM,
// 8 warps (2m x 4n), warp tile 64x32, ldmatrix, pitch 144B (conflict-free).
// ---------------------------------------------------------------------------
#define BM 128
#define BN 128
#define BK 64
#define STAGES 3
#define PITCH  144u
#define TILEB  (128u * PITCH)            // 18432 B per tile
#define STAGEB (2u * TILEB)              // A, B = 36864
#define SMEM_BYTES (STAGES * STAGEB)     // 110592

template<bool RELU, bool F16OUT>
__global__ __launch_bounds__(256, 2)
void gemm_fp16(const __half* __restrict__ A,
               const __half* __restrict__ B,
               const float* __restrict__ bias,
               float* __restrict__ Cf, __half* __restrict__ Ch,
               int K, int N)
{
    extern __shared__ char smem[];
    const uint32_t sb = smem_u32(smem);
    const int tid = threadIdx.x;
    const int wid = tid >> 5;
    const int lid = tid & 31;
    const int wm = wid & 1;
    const int wn = wid >> 1;
    const int mBase = blockIdx.y * BM;
    const int nBase = blockIdx.x * BN;

    auto load_stage = [&](int stage, int k0) {
        const uint32_t st = sb + stage * STAGEB;
        #pragma unroll
        for (int j = 0; j < 4; ++j) {
            int i = tid + 256 * j;            // 0..1023
            int r = i >> 3, c = i & 7;        // row 0..127, 16B chunk 0..7
            uint32_t off = (uint32_t)r * PITCH + (uint32_t)c * 16u;
            size_t ga = (size_t)(mBase + r) * K + k0 + c * 8;
            size_t gb = (size_t)(nBase + r) * K + k0 + c * 8;
            cp16(st + off,         A + ga);
            cp16(st + TILEB + off, B + gb);
        }
        asm volatile("cp.async.commit_group;" ::: "memory");
    };

    float acc[4][4][4];
    #pragma unroll
    for (int i = 0; i < 4; ++i)
        #pragma unroll
        for (int j = 0; j < 4; ++j)
            #pragma unroll
            for (int q = 0; q < 4; ++q) acc[i][j][q] = 0.f;

    const int NC = K / BK;
    load_stage(0, 0);
    load_stage(1, BK);

    const int lr16 = lid & 15;
    const uint32_t lcol = (uint32_t)(lid >> 4) * 16u;

    for (int c = 0; c < NC; ++c) {
        const int s = c % STAGES;
        asm volatile("cp.async.wait_group 1;" ::: "memory");
        __syncthreads();

        if (c + 2 < NC) load_stage((c + 2) % STAGES, (c + 2) * BK);

        const uint32_t st = sb + s * STAGEB;
        const uint32_t aAddr = st + (uint32_t)(wm * 64 + lr16) * PITCH + lcol;
        const uint32_t bAddr = st + TILEB + (uint32_t)(wn * 32 + lr16) * PITCH + lcol;

        #pragma unroll
        for (int kb = 0; kb < 4; ++kb) {
            const uint32_t cOff = (uint32_t)kb * 32u;
            uint32_t ah[4][4], bh[2][4];
            #pragma unroll
            for (int mi = 0; mi < 4; ++mi)
                ldsm4(ah[mi], aAddr + (uint32_t)mi * (16u * PITCH) + cOff);
            #pragma unroll
            for (int g = 0; g < 2; ++g)
                ldsm4(bh[g], bAddr + (uint32_t)g * (16u * PITCH) + cOff);
            #pragma unroll
            for (int mi = 0; mi < 4; ++mi)
                #pragma unroll
                for (int ni = 0; ni < 4; ++ni)
                    mma16816(acc[mi][ni], ah[mi], bh[ni >> 1][ni & 1], bh[ni >> 1][(ni & 1) + 2]);
        }
    }

    // ---- epilogue ----
    const int lr = lid >> 2;
    const int q2 = (lid & 3) * 2;
    #pragma unroll
    for (int mi = 0; mi < 4; ++mi) {
        #pragma unroll
        for (int half = 0; half < 2; ++half) {
            const int m = mBase + wm * 64 + mi * 16 + lr + half * 8;
            #pragma unroll
            for (int ni = 0; ni < 4; ++ni) {
                const int n = nBase + wn * 32 + ni * 8 + q2;
                float v0 = acc[mi][ni][half * 2 + 0] + bias[n];
                float v1 = acc[mi][ni][half * 2 + 1] + bias[n + 1];
                if (RELU) { v0 = fmaxf(v0, 0.f); v1 = fmaxf(v1, 0.f); }
                if (F16OUT) {
                    *reinterpret_cast<uint32_t*>(&Ch[(size_t)m * N + n]) =
                        pack_h2(__float2half(v0), __float2half(v1));
                } else {
                    *reinterpret_cast<float2*>(&Cf[(size_t)m * N + n]) = make_float2(v0, v1);
                }
            }
        }
    }
}

// ---------------------------------------------------------------------------
// Fused weight converter: W[K,N] fp32 -> WT[N,K] fp16, 8 matrices, one launch.
// ---------------------------------------------------------------------------
__global__ __launch_bounds__(256)
void convert_wT8(const float* __restrict__ W0, const float* __restrict__ W1,
                 const float* __restrict__ W2, const float* __restrict__ W3,
                 const float* __restrict__ W4, const float* __restrict__ W5,
                 const float* __restrict__ W6, const float* __restrict__ W7,
                 __half* __restrict__ T)
{
    const int z = blockIdx.z;
    const float* Ws[8] = {W0, W1, W2, W3, W4, W5, W6, W7};
    const float* W = Ws[z];
    const int K = (z & 1) ? HID : DHALF;
    const int N = (z & 1) ? DHALF : HID;
    const int n0 = (z & 1) ? blockIdx.y * 32 : blockIdx.x * 32;
    const int k0 = (z & 1) ? blockIdx.x * 32 : blockIdx.y * 32;
    __half* t_out = T + (size_t)z * WSLOT;

    __shared__ float t[32][33];
    const int tx = threadIdx.x & 31, ty = threadIdx.x >> 5;
    #pragma unroll
    for (int i = 0; i < 4; ++i)
        t[ty + i * 8][tx] = W[(size_t)(k0 + ty + i * 8) * N + n0 + tx];
    __syncthreads();
    #pragma unroll
    for (int i = 0; i < 4; ++i) {
        int n = n0 + ty + i * 8;
        t_out[(size_t)n * K + k0 + tx] = __float2half(t[tx][ty + i * 8]);
    }
}

__global__ __launch_bounds__(256)
void convert_act(const float* __restrict__ x, __half* __restrict__ a)
{
    const int m = blockIdx.x;
    const int j = threadIdx.x * 4;
    float4 v = *reinterpret_cast<const float4*>(&x[(size_t)m * XCOLS + DHALF + j]);
    uint2 o = make_uint2(pack_h2(__float2half(v.x), __float2half(v.y)),
                         pack_h2(__float2half(v.z), __float2half(v.w)));
    *reinterpret_cast<uint2*>(&a[(size_t)m * DHALF + j]) = o;
}

// ---------------------------------------------------------------------------
// Coupling epilogue: y = x_in * exp(tanh(spre)) + tval; logdet; opt fp16 act.
// ---------------------------------------------------------------------------
__global__ __launch_bounds__(256)
void ew_couple(const float* __restrict__ x,
               const float* __restrict__ spre,
               const float* __restrict__ tval,
               float* __restrict__ y,
               float* __restrict__ logdet,
               __half* __restrict__ act,
               int xColOff, int yColOff, int addLogdet, int writeAct)
{
    const int m = blockIdx.x;
    const int j = threadIdx.x * 4;

    float4 sp = *reinterpret_cast<const float4*>(&spre[(size_t)m * DHALF + j]);
    float4 tv = *reinterpret_cast<const float4*>(&tval[(size_t)m * DHALF + j]);
    float4 xv = *reinterpret_cast<const float4*>(&x[(size_t)m * XCOLS + xColOff + j]);

    float s0 = tanhf(sp.x), s1 = tanhf(sp.y), s2 = tanhf(sp.z), s3 = tanhf(sp.w);

    float4 o;
    o.x = xv.x * expf(s0) + tv.x;
    o.y = xv.y * expf(s1) + tv.y;
    o.z = xv.z * expf(s2) + tv.z;
    o.w = xv.w * expf(s3) + tv.w;
    *reinterpret_cast<float4*>(&y[(size_t)m * XCOLS + yColOff + j]) = o;

    if (writeAct) {
        uint2 av = make_uint2(pack_h2(__float2half(o.x), __float2half(o.y)),
                              pack_h2(__float2half(o.z), __float2half(o.w)));
        *reinterpret_cast<uint2*>(&act[(size_t)m * DHALF + j]) = av;
    }

    float lsum = s0 + s1 + s2 + s3;
    #pragma unroll
    for (int off = 16; off > 0; off >>= 1)
        lsum += __shfl_xor_sync(0xFFFFFFFFu, lsum, off);

    __shared__ float wsum[8];
    if ((threadIdx.x & 31) == 0) wsum[threadIdx.x >> 5] = lsum;
    __syncthreads();
    if (threadIdx.x == 0) {
        float tot = 0.0f;
        #pragma unroll
        for (int w = 0; w < 8; ++w) tot += wsum[w];
        if (addLogdet) logdet[m] += tot;
        else           logdet[m]  = tot;
    }
}

// ---------------------------------------------------------------------------
extern "C" void kernel_launch(void* const* d_in, const int* in_sizes, int n_in,
                              void* d_out, int out_size)
{
    (void)in_sizes; (void)n_in; (void)out_size;

    const float* x = (const float*)d_in[0];
    const float* W[8] = { (const float*)d_in[1],  (const float*)d_in[3],
                          (const float*)d_in[5],  (const float*)d_in[7],
                          (const float*)d_in[9],  (const float*)d_in[11],
                          (const float*)d_in[13], (const float*)d_in[15] };
    const float* B[8] = { (const float*)d_in[2],  (const float*)d_in[4],
                          (const float*)d_in[6],  (const float*)d_in[8],
                          (const float*)d_in[10], (const float*)d_in[12],
                          (const float*)d_in[14], (const float*)d_in[16] };

    float* y      = (float*)d_out;
    float* logdet = y + (size_t)BATCH * XCOLS;

    __half *act, *hid, *wt;
    float *sbuf, *tbuf;
    cudaGetSymbolAddress((void**)&act, g_act);
    cudaGetSymbolAddress((void**)&hid, g_hid);
    cudaGetSymbolAddress((void**)&wt,  g_wt);
    cudaGetSymbolAddress((void**)&sbuf, g_s);
    cudaGetSymbolAddress((void**)&tbuf, g_t);

    cudaFuncSetAttribute(gemm_fp16<true,  true >, cudaFuncAttributeMaxDynamicSharedMemorySize, SMEM_BYTES);
    cudaFuncSetAttribute(gemm_fp16<false, false>, cudaFuncAttributeMaxDynamicSharedMemorySize, SMEM_BYTES);

    convert_wT8<<<dim3(128, 32, 8), 256>>>(W[0], W[1], W[2], W[3], W[4], W[5], W[6], W[7], wt);
    convert_act<<<BATCH, 256>>>(x, act);

    dim3 blk(256);
    dim3 gridH(HID / BN,   BATCH / BM);
    dim3 gridD(DHALF / BN, BATCH / BM);

    // phase 1
    gemm_fp16<true,  true ><<<gridH, blk, SMEM_BYTES>>>(act, wt + 0 * WSLOT, B[0], nullptr, hid, DHALF, HID);
    gemm_fp16<false, false><<<gridD, blk, SMEM_BYTES>>>(hid, wt + 1 * WSLOT, B[1], sbuf, nullptr, HID, DHALF);
    gemm_fp16<true,  true ><<<gridH, blk, SMEM_BYTES>>>(act, wt + 2 * WSLOT, B[2], nullptr, hid, DHALF, HID);
    gemm_fp16<false, false><<<gridD, blk, SMEM_BYTES>>>(hid, wt + 3 * WSLOT, B[3], tbuf, nullptr, HID, DHALF);
    ew_couple<<<BATCH, 256>>>(x, sbuf, tbuf, y, logdet, act, 0, 0, 0, 1);

    // phase 2
    gemm_fp16<true,  true ><<<gridH, blk, SMEM_BYTES>>>(act, wt + 4 * WSLOT, B[4], nullptr, hid, DHALF, HID);
    gemm_fp16<false, false><<<gridD, blk, SMEM_BYTES>>>(hid, wt + 5 * WSLOT, B[5], sbuf, nullptr, HID, DHALF);
    gemm_fp16<true,  true ><<<gridH, blk, SMEM_BYTES>>>(act, wt + 6 * WSLOT, B[6], nullptr, hid, DHALF, HID);
    gemm_fp16<false, false><<<gridD, blk, SMEM_BYTES>>>(hid, wt + 7 * WSLOT, B[7], tbuf, nullptr, HID, DHALF);
    ew_couple<<<BATCH, 256>>>(x, sbuf, tbuf, y, logdet, nullptr, DHALF, DHALF, 1, 0);
}

// round 9
// speedup vs baseline: 2.9850x; 1.0248x over previous
#include <cuda_runtime.h>
#include <cuda_fp16.h>
#include <cstdint>
#include <math.h>

#define BATCH 8192
#define DHALF 1024
#define HID   4096
#define XCOLS 2048
#define WSLOT ((size_t)DHALF * HID)

// ---------------- scratch (device globals: allocation-free rule) -----------
__device__ __half g_act[(size_t)BATCH * DHALF];
__device__ __half g_hid[(size_t)BATCH * 2 * HID];     // s-half cols [0,4096), t-half [4096,8192)
__device__ __half g_wt[8 * WSLOT];
__device__ float g_s[(size_t)BATCH * DHALF];
__device__ float g_t[(size_t)BATCH * DHALF];

// ---------------- helpers ----------------------------------------------
__device__ __forceinline__ uint32_t smem_u32(const void* p) {
    uint32_t a;
    asm("{ .reg .u64 t; cvta.to.shared.u64 t, %1; cvt.u32.u64 %0, t; }" : "=r"(a) : "l"(p));
    return a;
}
__device__ __forceinline__ void cp16(uint32_t s, const void* g) {
    asm volatile("cp.async.cg.shared.global [%0], [%1], 16;" :: "r"(s), "l"(g));
}
__device__ __forceinline__ uint32_t pack_h2(__half a, __half b) {
    __half2 t = __halves2half2(a, b);
    return *reinterpret_cast<uint32_t*>(&t);
}
__device__ __forceinline__ void mma16816(float* d, const uint32_t* a, uint32_t b0, uint32_t b1) {
    asm volatile(
        "mma.sync.aligned.m16n8k16.row.col.f32.f16.f16.f32 "
        "{%0,%1,%2,%3}, {%4,%5,%6,%7}, {%8,%9}, {%0,%1,%2,%3};"
        : "+f"(d[0]), "+f"(d[1]), "+f"(d[2]), "+f"(d[3])
        : "r"(a[0]), "r"(a[1]), "r"(a[2]), "r"(a[3]), "r"(b0), "r"(b1));
}
__device__ __forceinline__ void ldsm4(uint32_t* r, uint32_t addr) {
    asm volatile("ldmatrix.sync.aligned.m8n8.x4.shared.b16 {%0,%1,%2,%3}, [%4];"
        : "=r"(r[0]), "=r"(r[1]), "=r"(r[2]), "=r"(r[3]) : "r"(addr));
}

#define PITCH 144u

// ---------------------------------------------------------------------------
// Layer-1 GEMM (merged s&t): hid[m, 0..8191] = relu(act @ [Ws|Wt]^T + [bs|bt])
// BM=128, BN=128, BK=64, 3 stages, 2 CTAs/SM, warp tile 64x32. K=1024, N=8192.
// ---------------------------------------------------------------------------
#define L1_K 1024
#define L1_N 8192
#define L1_TILEB (128u * PITCH)              // 18432
#define L1_STAGEB (2u * L1_TILEB)            // 36864
#define L1_SMEM (3u * L1_STAGEB)             // 110592

__global__ __launch_bounds__(256, 2)
void gemm_l1(const __half* __restrict__ A,
             const __half* __restrict__ B,        // wt slot base: rows 0..8191, ld=1024
             const float* __restrict__ bias0,     // s bias (cols 0..4095)
             const float* __restrict__ bias1,     // t bias (cols 4096..8191)
             __half* __restrict__ Ch)             // hid, ldc=8192
{
    extern __shared__ char smem[];
    const uint32_t sb = smem_u32(smem);
    const int tid = threadIdx.x;
    const int wid = tid >> 5;
    const int lid = tid & 31;
    const int wm = wid & 1;
    const int wn = wid >> 1;
    const int mBase = blockIdx.y * 128;
    const int nBase = blockIdx.x * 128;
    const float* __restrict__ bb = (nBase < HID) ? bias0 : bias1;

    auto load_stage = [&](int stage, int k0) {
        const uint32_t st = sb + stage * L1_STAGEB;
        #pragma unroll
        for (int j = 0; j < 4; ++j) {
            int i = tid + 256 * j;
            int r = i >> 3, c = i & 7;
            uint32_t off = (uint32_t)r * PITCH + (uint32_t)c * 16u;
            cp16(st + off,             A + (size_t)(mBase + r) * L1_K + k0 + c * 8);
            cp16(st + L1_TILEB + off,  B + (size_t)(nBase + r) * L1_K + k0 + c * 8);
        }
        asm volatile("cp.async.commit_group;" ::: "memory");
    };

    float acc[4][4][4];
    #pragma unroll
    for (int i = 0; i < 4; ++i)
        #pragma unroll
        for (int j = 0; j < 4; ++j)
            #pragma unroll
            for (int q = 0; q < 4; ++q) acc[i][j][q] = 0.f;

    const int NC = L1_K / 64;
    load_stage(0, 0);
    load_stage(1, 64);

    const int lr16 = lid & 15;
    const uint32_t lcol = (uint32_t)(lid >> 4) * 16u;

    for (int c = 0; c < NC; ++c) {
        const int s = c % 3;
        asm volatile("cp.async.wait_group 1;" ::: "memory");
        __syncthreads();
        if (c + 2 < NC) load_stage((c + 2) % 3, (c + 2) * 64);

        const uint32_t st = sb + s * L1_STAGEB;
        const uint32_t aAddr = st + (uint32_t)(wm * 64 + lr16) * PITCH + lcol;
        const uint32_t bAddr = st + L1_TILEB + (uint32_t)(wn * 32 + lr16) * PITCH + lcol;

        #pragma unroll
        for (int kb = 0; kb < 4; ++kb) {
            const uint32_t cOff = (uint32_t)kb * 32u;
            uint32_t ah[4][4], bh[2][4];
            #pragma unroll
            for (int mi = 0; mi < 4; ++mi)
                ldsm4(ah[mi], aAddr + (uint32_t)mi * (16u * PITCH) + cOff);
            #pragma unroll
            for (int g = 0; g < 2; ++g)
                ldsm4(bh[g], bAddr + (uint32_t)g * (16u * PITCH) + cOff);
            #pragma unroll
            for (int mi = 0; mi < 4; ++mi)
                #pragma unroll
                for (int ni = 0; ni < 4; ++ni)
                    mma16816(acc[mi][ni], ah[mi], bh[ni >> 1][ni & 1], bh[ni >> 1][(ni & 1) + 2]);
        }
    }

    const int lr = lid >> 2;
    const int q2 = (lid & 3) * 2;
    #pragma unroll
    for (int mi = 0; mi < 4; ++mi) {
        #pragma unroll
        for (int half = 0; half < 2; ++half) {
            const int m = mBase + wm * 64 + mi * 16 + lr + half * 8;
            #pragma unroll
            for (int ni = 0; ni < 4; ++ni) {
                const int n = nBase + wn * 32 + ni * 8 + q2;
                const int nb = n & (HID - 1);
                float v0 = fmaxf(acc[mi][ni][half * 2 + 0] + bb[nb],     0.f);
                float v1 = fmaxf(acc[mi][ni][half * 2 + 1] + bb[nb + 1], 0.f);
                *reinterpret_cast<uint32_t*>(&Ch[(size_t)m * L1_N + n]) =
                    pack_h2(__float2half(v0), __float2half(v1));
            }
        }
    }
}

// ---------------------------------------------------------------------------
// Layer-2 GEMM, z-batched (z=0: s-chain, z=1: t-chain):
// C_z[m, 0..1023] = hid[:, z*4096 + k] @ Wz^T + bias_z   (fp32 out)
// BM=64, BN=128, BK=64, 4 stages, 2 CTAs/SM, warp tile 32x32. K=4096.
// ---------------------------------------------------------------------------
#define L2_K 4096
#define L2_ATILE (64u * PITCH)               // 9216
#define L2_BTILE (128u * PITCH)              // 18432
#define L2_STAGEB (L2_ATILE + L2_BTILE)      // 27648
#define L2_SMEM (4u * L2_STAGEB)             // 110592

__global__ __launch_bounds__(256, 2)
void gemm_l2(const __half* __restrict__ Ab,   // g_hid base (ld = 8192)
             const __half* __restrict__ Wb,   // wt slot base for z=0; z=1 at +WSLOT
             const float* __restrict__ bias0, const float* __restrict__ bias1,
             float* __restrict__ C0, float* __restrict__ C1)
{
    extern __shared__ char smem[];
    const uint32_t sb = smem_u32(smem);
    const int tid = threadIdx.x;
    const int wid = tid >> 5;
    const int lid = tid & 31;
    const int wm = wid & 1;          // 2 m-bands of 32
    const int wn = wid >> 1;         // 4 n-bands of 32
    const int z  = blockIdx.z;
    const int mBase = blockIdx.y * 64;
    const int nBase = blockIdx.x * 128;

    const __half* __restrict__ A = Ab + (size_t)z * HID;     // column offset
    const __half* __restrict__ B = Wb + (size_t)z * WSLOT;
    const float* __restrict__ bias = z ? bias1 : bias0;
    float* __restrict__ C = z ? C1 : C0;

    auto load_stage = [&](int stage, int k0) {
        const uint32_t st = sb + stage * L2_STAGEB;
        #pragma unroll
        for (int j = 0; j < 2; ++j) {                 // A: 64 rows x 8 chunks
            int i = tid + 256 * j;
            int r = i >> 3, c = i & 7;
            uint32_t off = (uint32_t)r * PITCH + (uint32_t)c * 16u;
            cp16(st + off, A + (size_t)(mBase + r) * (2 * HID) + k0 + c * 8);
        }
        #pragma unroll
        for (int j = 0; j < 4; ++j) {                 // B: 128 rows x 8 chunks
            int i = tid + 256 * j;
            int r = i >> 3, c = i & 7;
            uint32_t off = (uint32_t)r * PITCH + (uint32_t)c * 16u;
            cp16(st + L2_ATILE + off, B + (size_t)(nBase + r) * L2_K + k0 + c * 8);
        }
        asm volatile("cp.async.commit_group;" ::: "memory");
    };

    float acc[2][4][4];
    #pragma unroll
    for (int i = 0; i < 2; ++i)
        #pragma unroll
        for (int j = 0; j < 4; ++j)
            #pragma unroll
            for (int q = 0; q < 4; ++q) acc[i][j][q] = 0.f;

    const int NC = L2_K / 64;
    load_stage(0, 0);
    load_stage(1, 64);
    load_stage(2, 128);

    const int lr16 = lid & 15;
    const uint32_t lcol = (uint32_t)(lid >> 4) * 16u;

    for (int c = 0; c < NC; ++c) {
        const int s = c & 3;
        asm volatile("cp.async.wait_group 2;" ::: "memory");
        __syncthreads();
        if (c + 3 < NC) load_stage((c + 3) & 3, (c + 3) * 64);

        const uint32_t st = sb + s * L2_STAGEB;
        const uint32_t aAddr = st + (uint32_t)(wm * 32 + lr16) * PITCH + lcol;
        const uint32_t bAddr = st + L2_ATILE + (uint32_t)(wn * 32 + lr16) * PITCH + lcol;

        #pragma unroll
        for (int kb = 0; kb < 4; ++kb) {
            const uint32_t cOff = (uint32_t)kb * 32u;
            uint32_t ah[2][4], bh[2][4];
            #pragma unroll
            for (int mi = 0; mi < 2; ++mi)
                ldsm4(ah[mi], aAddr + (uint32_t)mi * (16u * PITCH) + cOff);
            #pragma unroll
            for (int g = 0; g < 2; ++g)
                ldsm4(bh[g], bAddr + (uint32_t)g * (16u * PITCH) + cOff);
            #pragma unroll
            for (int mi = 0; mi < 2; ++mi)
                #pragma unroll
                for (int ni = 0; ni < 4; ++ni)
                    mma16816(acc[mi][ni], ah[mi], bh[ni >> 1][ni & 1], bh[ni >> 1][(ni & 1) + 2]);
        }
    }

    const int lr = lid >> 2;
    const int q2 = (lid & 3) * 2;
    #pragma unroll
    for (int mi = 0; mi < 2; ++mi) {
        #pragma unroll
        for (int half = 0; half < 2; ++half) {
            const int m = mBase + wm * 32 + mi * 16 + lr + half * 8;
            #pragma unroll
            for (int ni = 0; ni < 4; ++ni) {
                const int n = nBase + wn * 32 + ni * 8 + q2;
                float v0 = acc[mi][ni][half * 2 + 0] + bias[n];
                float v1 = acc[mi][ni][half * 2 + 1] + bias[n + 1];
                *reinterpret_cast<float2*>(&C[(size_t)m * DHALF + n]) = make_float2(v0, v1);
            }
        }
    }
}

// ---------------------------------------------------------------------------
// Weight converter: 8 matrices, slot order (s1W1,t1W1,s1W2,t1W2,s2W1,t2W1,s2W2,t2W2).
// Slots {0,1,4,5}: W1-type (K=1024,N=4096); {2,3,6,7}: W2-type (K=4096,N=1024).
// uint4-vectorized writes.
// ---------------------------------------------------------------------------
__global__ __launch_bounds__(256)
void convert_wT8(const float* __restrict__ W0, const float* __restrict__ W1,
                 const float* __restrict__ W2, const float* __restrict__ W3,
                 const float* __restrict__ W4, const float* __restrict__ W5,
                 const float* __restrict__ W6, const float* __restrict__ W7,
                 __half* __restrict__ T)
{
    const int z = blockIdx.z;
    const float* Ws[8] = {W0, W1, W2, W3, W4, W5, W6, W7};
    const float* W = Ws[z];
    const int typeW2 = (z >> 1) & 1;
    const int K = typeW2 ? HID : DHALF;
    const int N = typeW2 ? DHALF : HID;
    const int n0 = typeW2 ? blockIdx.y * 32 : blockIdx.x * 32;
    const int k0 = typeW2 ? blockIdx.x * 32 : blockIdx.y * 32;
    __half* t_out = T + (size_t)z * WSLOT;

    __shared__ float t[32][33];
    const int tx = threadIdx.x & 31, ty = threadIdx.x >> 5;
    #pragma unroll
    for (int i = 0; i < 4; ++i)
        t[ty + i * 8][tx] = W[(size_t)(k0 + ty + i * 8) * N + n0 + tx];
    __syncthreads();

    const int tid = threadIdx.x;
    if (tid < 128) {
        const int n  = tid >> 2;          // 0..31
        const int kc = (tid & 3) * 8;     // 0,8,16,24
        uint4 v;
        v.x = pack_h2(__float2half(t[kc + 0][n]), __float2half(t[kc + 1][n]));
        v.y = pack_h2(__float2half(t[kc + 2][n]), __float2half(t[kc + 3][n]));
        v.z = pack_h2(__float2half(t[kc + 4][n]), __float2half(t[kc + 5][n]));
        v.w = pack_h2(__float2half(t[kc + 6][n]), __float2half(t[kc + 7][n]));
        *reinterpret_cast<uint4*>(&t_out[(size_t)(n0 + n) * K + k0 + kc]) = v;
    }
}

__global__ __launch_bounds__(256)
void convert_act(const float* __restrict__ x, __half* __restrict__ a)
{
    const int m = blockIdx.x;
    const int j = threadIdx.x * 4;
    float4 v = *reinterpret_cast<const float4*>(&x[(size_t)m * XCOLS + DHALF + j]);
    uint2 o = make_uint2(pack_h2(__float2half(v.x), __float2half(v.y)),
                         pack_h2(__float2half(v.z), __float2half(v.w)));
    *reinterpret_cast<uint2*>(&a[(size_t)m * DHALF + j]) = o;
}

// ---------------------------------------------------------------------------
// Coupling epilogue
// ---------------------------------------------------------------------------
__global__ __launch_bounds__(256)
void ew_couple(const float* __restrict__ x,
               const float* __restrict__ spre,
               const float* __restrict__ tval,
               float* __restrict__ y,
               float* __restrict__ logdet,
               __half* __restrict__ act,
               int xColOff, int yColOff, int addLogdet, int writeAct)
{
    const int m = blockIdx.x;
    const int j = threadIdx.x * 4;

    float4 sp = *reinterpret_cast<const float4*>(&spre[(size_t)m * DHALF + j]);
    float4 tv = *reinterpret_cast<const float4*>(&tval[(size_t)m * DHALF + j]);
    float4 xv = *reinterpret_cast<const float4*>(&x[(size_t)m * XCOLS + xColOff + j]);

    float s0 = tanhf(sp.x), s1 = tanhf(sp.y), s2 = tanhf(sp.z), s3 = tanhf(sp.w);

    float4 o;
    o.x = xv.x * expf(s0) + tv.x;
    o.y = xv.y * expf(s1) + tv.y;
    o.z = xv.z * expf(s2) + tv.z;
    o.w = xv.w * expf(s3) + tv.w;
    *reinterpret_cast<float4*>(&y[(size_t)m * XCOLS + yColOff + j]) = o;

    if (writeAct) {
        uint2 av = make_uint2(pack_h2(__float2half(o.x), __float2half(o.y)),
                              pack_h2(__float2half(o.z), __float2half(o.w)));
        *reinterpret_cast<uint2*>(&act[(size_t)m * DHALF + j]) = av;
    }

    float lsum = s0 + s1 + s2 + s3;
    #pragma unroll
    for (int off = 16; off > 0; off >>= 1)
        lsum += __shfl_xor_sync(0xFFFFFFFFu, lsum, off);

    __shared__ float wsum[8];
    if ((threadIdx.x & 31) == 0) wsum[threadIdx.x >> 5] = lsum;
    __syncthreads();
    if (threadIdx.x == 0) {
        float tot = 0.0f;
        #pragma unroll
        for (int w = 0; w < 8; ++w) tot += wsum[w];
        if (addLogdet) logdet[m] += tot;
        else           logdet[m]  = tot;
    }
}

// ---------------------------------------------------------------------------
extern "C" void kernel_launch(void* const* d_in, const int* in_sizes, int n_in,
                              void* d_out, int out_size)
{
    (void)in_sizes; (void)n_in; (void)out_size;

    const float* x = (const float*)d_in[0];
    // weights in slot order: s1W1, t1W1, s1W2, t1W2, s2W1, t2W1, s2W2, t2W2
    const float* Wslot[8] = { (const float*)d_in[1],  (const float*)d_in[5],
                              (const float*)d_in[3],  (const float*)d_in[7],
                              (const float*)d_in[9],  (const float*)d_in[13],
                              (const float*)d_in[11], (const float*)d_in[15] };
    const float* s1_b1 = (const float*)d_in[2];
    const float* s1_b2 = (const float*)d_in[4];
    const float* t1_b1 = (const float*)d_in[6];
    const float* t1_b2 = (const float*)d_in[8];
    const float* s2_b1 = (const float*)d_in[10];
    const float* s2_b2 = (const float*)d_in[12];
    const float* t2_b1 = (const float*)d_in[14];
    const float* t2_b2 = (const float*)d_in[16];

    float* y      = (float*)d_out;
    float* logdet = y + (size_t)BATCH * XCOLS;

    __half *act, *hid, *wt;
    float *sbuf, *tbuf;
    cudaGetSymbolAddress((void**)&act, g_act);
    cudaGetSymbolAddress((void**)&hid, g_hid);
    cudaGetSymbolAddress((void**)&wt,  g_wt);
    cudaGetSymbolAddress((void**)&sbuf, g_s);
    cudaGetSymbolAddress((void**)&tbuf, g_t);

    cudaFuncSetAttribute(gemm_l1, cudaFuncAttributeMaxDynamicSharedMemorySize, L1_SMEM);
    cudaFuncSetAttribute(gemm_l2, cudaFuncAttributeMaxDynamicSharedMemorySize, L2_SMEM);

    convert_wT8<<<dim3(128, 32, 8), 256>>>(Wslot[0], Wslot[1], Wslot[2], Wslot[3],
                                           Wslot[4], Wslot[5], Wslot[6], Wslot[7], wt);
    convert_act<<<BATCH, 256>>>(x, act);

    dim3 blk(256);
    dim3 gridL1(L1_N / 128, BATCH / 128);        // 64 x 64
    dim3 gridL2(DHALF / 128, BATCH / 64, 2);     // 8 x 128 x 2

    // phase 1: hid = relu(act@[s1W1|t1W1]^T + b); sbuf/tbuf = hid_z @ W2_z^T + b2_z
    gemm_l1<<<gridL1, blk, L1_SMEM>>>(act, wt + 0 * WSLOT, s1_b1, t1_b1, hid);
    gemm_l2<<<gridL2, blk, L2_SMEM>>>(hid, wt + 2 * WSLOT, s1_b2, t1_b2, sbuf, tbuf);
    ew_couple<<<BATCH, 256>>>(x, sbuf, tbuf, y, logdet, act, 0, 0, 0, 1);

    // phase 2
    gemm_l1<<<gridL1, blk, L1_SMEM>>>(act, wt + 4 * WSLOT, s2_b1, t2_b1, hid);
    gemm_l2<<<gridL2, blk, L2_SMEM>>>(hid, wt + 6 * WSLOT, s2_b2, t2_b2, sbuf, tbuf);
    ew_couple<<<BATCH, 256>>>(x, sbuf, tbuf, y, logdet, nullptr, DHALF, DHALF, 1, 0);
}